// round 7
// baseline (speedup 1.0000x reference)
#include <cuda_runtime.h>
#include <cuda_fp16.h>
#include <stdint.h>

#define BB 256
#define LL 336
#define NIN 8
#define HH 512
#define G4 2048
#define PL 96
#define NBE 128
#define NBD 128

__device__ __half g_h0[2][BB*HH];
__device__ __half g_h1[2][BB*HH];
__device__ float  g_c1f[BB*HH];
__device__ __half g_ctx[BB*HH];
__device__ float  g_yprev[BB];
__device__ __half g_enc[(size_t)LL*BB*HH];
__device__ __half g_xp[(size_t)LL*BB*G4];
__device__ unsigned g_bar_enc, g_bar_dec;

__device__ __forceinline__ float sigf(float x) { return 1.f / (1.f + __expf(-x)); }

__device__ __forceinline__ void gridbar(unsigned* bar, unsigned& round, unsigned nblk) {
    round++;
    __syncthreads();
    __threadfence();
    if (threadIdx.x == 0) {
        unsigned target = round * nblk;
        atomicAdd(bar, 1u);
        while (*(volatile unsigned*)bar < target) { }
        __threadfence();
    }
    __syncthreads();
}

__device__ __forceinline__ uint32_t smem_u32(const void* p) {
    uint32_t a;
    asm("{ .reg .u64 t; cvta.to.shared.u64 t, %1; cvt.u32.u64 %0, t; }" : "=r"(a) : "l"(p));
    return a;
}

__device__ __forceinline__ void mma16(float c[4], const uint32_t a[4], const uint32_t b[2]) {
    asm volatile(
        "mma.sync.aligned.m16n8k16.row.col.f32.f16.f16.f32 "
        "{%0,%1,%2,%3},{%4,%5,%6,%7},{%8,%9},{%0,%1,%2,%3};"
        : "+f"(c[0]), "+f"(c[1]), "+f"(c[2]), "+f"(c[3])
        : "r"(a[0]), "r"(a[1]), "r"(a[2]), "r"(a[3]), "r"(b[0]), "r"(b[1]));
}

#define LDSM4(r0, r1, r2, r3, addr) \
    asm volatile("ldmatrix.sync.aligned.m8n8.x4.shared.b16 {%0,%1,%2,%3},[%4];" \
                 : "=r"(r0), "=r"(r1), "=r"(r2), "=r"(r3) : "r"(addr))

#define CP_COMMIT asm volatile("cp.async.commit_group;\n")
#define CP_WAIT1  asm volatile("cp.async.wait_group 1;\n")
#define CP_WAIT0  asm volatile("cp.async.wait_group 0;\n")

// gate/hidden permutation within a CTA's 32 columns
__device__ __forceinline__ int colgate(int c) { return (c & 1) | (((c >> 3) & 1) << 1); }
__device__ __forceinline__ int coldn(int c)   { return ((c >> 4) & 1) * 4 + ((c >> 1) & 3); }

// ---------------- prep + xp ----------------
__global__ void prep_kernel() {
    int i = blockIdx.x * blockDim.x + threadIdx.x;
    if (i < BB * HH) {
        g_h0[0][i] = __float2half(0.f);
        g_h1[0][i] = __float2half(0.f);
    }
    if (i == 0) { g_bar_enc = 0u; g_bar_dec = 0u; }
}

__global__ void xp_kernel(const float* __restrict__ x, const float* __restrict__ Wih0,
                          const float* __restrict__ bi0, const float* __restrict__ bh0) {
    int t = blockIdx.x, bch = blockIdx.y * 32, tid = threadIdx.x;
    __shared__ float xs[256];
    {
        int b8 = tid >> 3, k8 = tid & 7;
        xs[tid] = x[((size_t)(bch + b8) * LL + t) * NIN + k8];
    }
    __syncthreads();
    float wr[8][8], bs[8];
    int c0 = tid * 8;
#pragma unroll
    for (int cc = 0; cc < 8; cc++) {
        int cg = c0 + cc;
        int nb = cg >> 5, c = cg & 31;
        int row = colgate(c) * HH + nb * 8 + coldn(c);
#pragma unroll
        for (int k = 0; k < 8; k++) wr[cc][k] = Wih0[row * NIN + k];
        bs[cc] = bi0[row] + bh0[row];
    }
    for (int b = 0; b < 32; b++) {
        __half h8[8];
#pragma unroll
        for (int cc = 0; cc < 8; cc++) {
            float a = bs[cc];
#pragma unroll
            for (int k = 0; k < 8; k++) a += wr[cc][k] * xs[b * 8 + k];
            h8[cc] = __float2half(a);
        }
        *(uint4*)(g_xp + ((size_t)t * BB + bch + b) * G4 + c0) = *(uint4*)h8;
    }
}

// ---------------- ENCODER: unified 128-CTA, ldmatrix, fused cells ----------------
// smem bytes: WL0 33280 | WL1 66048 | Abuf 2x34816 | ht0 2048 | ht1 2048 | bias1 128
#define OF_WL1 33280
#define OF_AB  99328
#define OF_HT0 168960
#define OF_HT1 171008
#define OF_B1  173056
#define ENC_SMEM 173440
#define ABUFB 34816

__device__ __forceinline__ void stageA(uint32_t dstb, const __half* __restrict__ src) {
    int t = threadIdx.x;
    int row = t >> 1, hp = t & 1;
    const char* g = (const char*)(src + (size_t)row * HH + hp * 64);
    uint32_t d = dstb + (uint32_t)(row * 136 + hp * 64) * 2;
#pragma unroll
    for (int i = 0; i < 8; i++)
        asm volatile("cp.async.cg.shared.global [%0],[%1],16;"
                     :: "r"(d + i * 16), "l"(g + i * 16));
}

__global__ void __launch_bounds__(256, 1) enc_persistent(
    const float* __restrict__ Whh0, const float* __restrict__ Wih1,
    const float* __restrict__ Whh1,
    const float* __restrict__ bi1, const float* __restrict__ bh1) {
    extern __shared__ __align__(16) char smc[];
    __half* WL0 = (__half*)smc;
    __half* WL1 = (__half*)(smc + OF_WL1);
    __half* ht0 = (__half*)(smc + OF_HT0);
    __half* ht1 = (__half*)(smc + OF_HT1);
    float* bias1 = (float*)(smc + OF_B1);
    uint32_t smb = smem_u32(smc);

    int bx = blockIdx.x, tid = threadIdx.x;
    int lane = tid & 31, wid = tid >> 5;
    int wm = wid >> 1, wn = wid & 1;
    int i4 = lane >> 3, r8 = lane & 7;
    int er = lane >> 2, ec = lane & 3;
    int mh = bx & 1, nb = bx >> 1;

    // ---- weights -> smem fp16 ----
    for (int idx = tid; idx < 32 * 128; idx += 256) {
        int c = idx >> 7, k4 = (idx & 127) * 4;
        int row = colgate(c) * HH + nb * 8 + coldn(c);
        float4 w = *(const float4*)(Whh0 + (size_t)row * HH + k4);
        __half* d = WL0 + c * 520 + k4;
        d[0] = __float2half(w.x); d[1] = __float2half(w.y);
        d[2] = __float2half(w.z); d[3] = __float2half(w.w);
    }
    for (int idx = tid; idx < 32 * 256; idx += 256) {
        int c = idx >> 8, k4 = (idx & 255) * 4;
        int row = colgate(c) * HH + nb * 8 + coldn(c);
        const float* srcW = (k4 < HH) ? Wih1 + (size_t)row * HH + k4
                                      : Whh1 + (size_t)row * HH + (k4 - HH);
        float4 w = *(const float4*)srcW;
        __half* d = WL1 + c * 1032 + k4;
        d[0] = __float2half(w.x); d[1] = __float2half(w.y);
        d[2] = __float2half(w.z); d[3] = __float2half(w.w);
    }
    if (tid < 32) {
        int row = colgate(tid) * HH + nb * 8 + coldn(tid);
        bias1[tid] = bi1[row] + bh1[row];
    }
    __syncthreads();

    // ldmatrix lane offsets (bytes)
    uint32_t aoff0 = (uint32_t)((wm * 32 + (i4 & 1) * 8 + r8) * 136 + ((i4 >> 1) & 1) * 8) * 2;
    uint32_t aoff1 = aoff0 + 16 * 136 * 2;
    int colB = wn * 16 + ((i4 >> 1) & 1) * 8 + r8;
    int khB = (i4 & 1) * 8;
    uint32_t bo0 = smb + (uint32_t)(colB * 520 + khB) * 2;
    uint32_t bo1 = smb + OF_WL1 + (uint32_t)(colB * 1032 + khB) * 2;

    float cst0[4], cst1[4];
#pragma unroll
    for (int i = 0; i < 4; i++) { cst0[i] = 0.f; cst1[i] = 0.f; }

    unsigned round = 0;
    for (int s = 0; s <= LL; s++) {
        bool doL0 = (s < LL), doL1 = (s >= 1);
        int nch = doL1 ? 8 : 4;
        const __half* h0p = g_h0[s & 1] + (size_t)mh * 128 * HH;
        const __half* h1p = g_h1[(s + 1) & 1] + (size_t)mh * 128 * HH;

        float aL0[2][2][4], aL1[2][2][4];
#pragma unroll
        for (int a = 0; a < 2; a++)
#pragma unroll
            for (int b = 0; b < 2; b++)
#pragma unroll
                for (int q = 0; q < 4; q++) { aL0[a][b][q] = 0.f; aL1[a][b][q] = 0.f; }

        stageA(smb + OF_AB, h0p);
        CP_COMMIT;
        for (int ch = 0; ch < nch; ch++) {
            if (ch + 1 < nch) {
                const __half* sp = (ch + 1 < 4) ? h0p + (ch + 1) * 128 : h1p + (ch - 3) * 128;
                stageA(smb + OF_AB + ((ch + 1) & 1) * ABUFB, sp);
                CP_COMMIT; CP_WAIT1;
            } else {
                CP_WAIT0;
            }
            __syncthreads();
            uint32_t ab = smb + OF_AB + (ch & 1) * ABUFB;
            bool dL0 = doL0 && ch < 4;
            uint32_t wkb = (uint32_t)(ch * 128) * 2;
#pragma unroll
            for (int j = 0; j < 8; j++) {
                uint32_t a[2][4];
                LDSM4(a[0][0], a[0][1], a[0][2], a[0][3], ab + aoff0 + j * 32);
                LDSM4(a[1][0], a[1][1], a[1][2], a[1][3], ab + aoff1 + j * 32);
                if (dL0) {
                    uint32_t b[4];
                    LDSM4(b[0], b[1], b[2], b[3], bo0 + wkb + j * 32);
#pragma unroll
                    for (int mi = 0; mi < 2; mi++) {
                        mma16(aL0[mi][0], a[mi], b);
                        mma16(aL0[mi][1], a[mi], b + 2);
                    }
                }
                if (doL1) {
                    uint32_t b[4];
                    LDSM4(b[0], b[1], b[2], b[3], bo1 + wkb + j * 32);
#pragma unroll
                    for (int mi = 0; mi < 2; mi++) {
                        mma16(aL1[mi][0], a[mi], b);
                        mma16(aL1[mi][1], a[mi], b + 2);
                    }
                }
            }
            __syncthreads();
        }

        // ---- fused cells ----
        int dnl = wn * 4 + ec;
        if (doL0) {
            const __half* xb = g_xp + (size_t)s * BB * G4;
#pragma unroll
            for (int mi = 0; mi < 2; mi++)
#pragma unroll
                for (int rh = 0; rh < 2; rh++) {
                    int row = wm * 32 + mi * 16 + rh * 8 + er;
                    int b = mh * 128 + row;
                    const __half* xpp = xb + (size_t)b * G4 + nb * 32 + wn * 16 + 2 * ec;
                    float2 flo = __half22float2(*(const __half2*)xpp);
                    float2 fhi = __half22float2(*(const __half2*)(xpp + 8));
                    float g0 = aL0[mi][0][rh * 2]     + flo.x;
                    float g1 = aL0[mi][0][rh * 2 + 1] + flo.y;
                    float g2 = aL0[mi][1][rh * 2]     + fhi.x;
                    float g3 = aL0[mi][1][rh * 2 + 1] + fhi.y;
                    float ig = sigf(g0), fg = sigf(g1);
                    float gg = tanhf(g2), og = sigf(g3);
                    int ix = mi * 2 + rh;
                    float cv = fg * cst0[ix] + ig * gg;
                    cst0[ix] = cv;
                    ht0[row * 8 + dnl] = __float2half(og * tanhf(cv));
                }
        }
        if (doL1) {
            float b0 = bias1[wn * 16 + 2 * ec];
            float b1 = bias1[wn * 16 + 2 * ec + 1];
            float b2 = bias1[wn * 16 + 2 * ec + 8];
            float b3 = bias1[wn * 16 + 2 * ec + 9];
#pragma unroll
            for (int mi = 0; mi < 2; mi++)
#pragma unroll
                for (int rh = 0; rh < 2; rh++) {
                    int row = wm * 32 + mi * 16 + rh * 8 + er;
                    int b = mh * 128 + row;
                    float g0 = aL1[mi][0][rh * 2]     + b0;
                    float g1 = aL1[mi][0][rh * 2 + 1] + b1;
                    float g2 = aL1[mi][1][rh * 2]     + b2;
                    float g3 = aL1[mi][1][rh * 2 + 1] + b3;
                    float ig = sigf(g0), fg = sigf(g1);
                    float gg = tanhf(g2), og = sigf(g3);
                    int ix = mi * 2 + rh;
                    float cv = fg * cst1[ix] + ig * gg;
                    cst1[ix] = cv;
                    ht1[row * 8 + dnl] = __float2half(og * tanhf(cv));
                    if (s == LL) g_c1f[(size_t)b * HH + nb * 8 + dnl] = cv;
                }
        }
        __syncthreads();
        if (doL0 && tid < 128) {
            uint4 v = *(uint4*)(ht0 + tid * 8);
            *(uint4*)(g_h0[(s + 1) & 1] + (size_t)(mh * 128 + tid) * HH + nb * 8) = v;
        }
        if (doL1 && tid >= 128) {
            int row = tid - 128;
            uint4 v = *(uint4*)(ht1 + row * 8);
            size_t o = (size_t)(mh * 128 + row) * HH + nb * 8;
            *(uint4*)(g_h1[s & 1] + o) = v;
            *(uint4*)(g_enc + (size_t)(s - 1) * BB * HH + o) = v;
        }
        gridbar(&g_bar_enc, round, NBE);
    }
}

// ---------------- DECODER (R5, unchanged) ----------------
__device__ __forceinline__ void stage64(__half* dst, const __half* __restrict__ src) {
    int t = threadIdx.x;
    int row = t >> 1;
    int off = (t & 1) * 32;
    const __half* g = src + (size_t)row * HH + off;
    unsigned sa = (unsigned)__cvta_generic_to_shared(dst + row * 72 + off);
#pragma unroll
    for (int i = 0; i < 4; i++)
        asm volatile("cp.async.cg.shared.global [%0], [%1], 16;\n"
                     :: "r"(sa + i * 16), "l"(g + i * 8));
}

template<int NT, int NCH, int KPAD>
__device__ __forceinline__ void gemm16(const __half* __restrict__ srcA,
                                       const __half* __restrict__ srcB,
                                       __half* As, const __half* Ws,
                                       float (&acc)[2][NT][4],
                                       int wm, int wn, int lr, int lc2) {
    stage64(As, srcA);
    CP_COMMIT;
    const __half* Wp = Ws + (size_t)(wn * NT * 8 + lr) * KPAD + lc2;
    for (int kc = 0; kc < NCH; kc++) {
        if (kc + 1 < NCH) {
            int ko = (kc + 1) * 64;
            const __half* s = (srcB == nullptr || ko < HH) ? srcA + ko : srcB + (ko - HH);
            stage64(As + ((kc + 1) & 1) * (128 * 72), s);
            CP_COMMIT; CP_WAIT1;
        } else {
            CP_WAIT0;
        }
        __syncthreads();
        const __half* Ab = As + (kc & 1) * (128 * 72) + (size_t)(wm * 32 + lr) * 72 + lc2;
        int kb = kc * 64;
#pragma unroll
        for (int ko = 0; ko < 64; ko += 16) {
            uint32_t a[2][4], b[NT][2];
#pragma unroll
            for (int mi = 0; mi < 2; mi++) {
                const __half* ap = Ab + mi * 16 * 72 + ko;
                a[mi][0] = *(const uint32_t*)(ap);
                a[mi][1] = *(const uint32_t*)(ap + 8 * 72);
                a[mi][2] = *(const uint32_t*)(ap + 8);
                a[mi][3] = *(const uint32_t*)(ap + 8 * 72 + 8);
            }
#pragma unroll
            for (int ni = 0; ni < NT; ni++) {
                const __half* bp = Wp + (size_t)ni * 8 * KPAD + kb + ko;
                b[ni][0] = *(const uint32_t*)(bp);
                b[ni][1] = *(const uint32_t*)(bp + 8);
            }
#pragma unroll
            for (int mi = 0; mi < 2; mi++)
#pragma unroll
                for (int ni = 0; ni < NT; ni++)
                    mma16(acc[mi][ni], a[mi], b[ni]);
        }
        __syncthreads();
    }
}

__device__ __forceinline__ float dot8r(uint4 v, const float* s) {
    const __half2* h2 = (const __half2*)&v;
    float r = 0.f;
#pragma unroll
    for (int i = 0; i < 4; i++) {
        float2 f = __half22float2(h2[i]);
        r += f.x * s[2 * i] + f.y * s[2 * i + 1];
    }
    return r;
}

__device__ void attn_one(int ds, int b, bool full, const float* __restrict__ Wfc,
                         const float* __restrict__ bfc, float* __restrict__ out,
                         float* pa, float* pms) {
    int tid = threadIdx.x, lane = tid & 31, w = tid >> 5;
    const __half* hd = g_h1[ds & 1] + (size_t)b * HH;
    float hreg[16];
#pragma unroll
    for (int i = 0; i < 8; i++) {
        hreg[i]     = __half2float(hd[lane * 8 + i]);
        hreg[8 + i] = __half2float(hd[256 + lane * 8 + i]);
    }
    if (w == 0) {
        float yv = 0.f;
#pragma unroll
        for (int i = 0; i < 8; i++)
            yv += hreg[i] * Wfc[lane * 8 + i] + hreg[8 + i] * Wfc[256 + lane * 8 + i];
#pragma unroll
        for (int off = 16; off; off >>= 1) yv += __shfl_xor_sync(0xffffffffu, yv, off);
        if (lane == 0) {
            float y = yv + bfc[0];
            if (ds > 0) out[b * PL + ds - 1] = y;
            g_yprev[b] = (ds == 0) ? 0.f : y;
        }
    }
    if (!full) return;

    float M = -1e30f, S = 0.f, C[16];
#pragma unroll
    for (int i = 0; i < 16; i++) C[i] = 0.f;
    for (int l = w; l < LL; l += 8) {
        const uint4* e4 = (const uint4*)(g_enc + ((size_t)l * BB + b) * HH);
        uint4 v0 = e4[lane];
        uint4 v1 = e4[lane + 32];
        float s1 = dot8r(v0, hreg) + dot8r(v1, hreg + 8);
#pragma unroll
        for (int off = 16; off; off >>= 1) s1 += __shfl_xor_sync(0xffffffffu, s1, off);
        float mn = fmaxf(M, s1);
        float r = __expf(M - mn);
        float e = __expf(s1 - mn);
        S = S * r + e;
        const __half2* ha = (const __half2*)&v0;
        const __half2* hb = (const __half2*)&v1;
#pragma unroll
        for (int i = 0; i < 4; i++) {
            float2 f = __half22float2(ha[i]);
            C[2 * i]     = C[2 * i] * r + e * f.x;
            C[2 * i + 1] = C[2 * i + 1] * r + e * f.y;
            float2 f2 = __half22float2(hb[i]);
            C[8 + 2 * i]     = C[8 + 2 * i] * r + e * f2.x;
            C[8 + 2 * i + 1] = C[8 + 2 * i + 1] * r + e * f2.y;
        }
        M = mn;
    }
    if (lane == 0) { pms[w * 2] = M; pms[w * 2 + 1] = S; }
#pragma unroll
    for (int i = 0; i < 8; i++) {
        pa[w * 512 + lane * 8 + i]       = C[i];
        pa[w * 512 + 256 + lane * 8 + i] = C[8 + i];
    }
    __syncthreads();
    float Mg = -1e30f;
#pragma unroll
    for (int ww = 0; ww < 8; ww++) Mg = fmaxf(Mg, pms[ww * 2]);
    float Sg = 0.f;
    float scl[8];
#pragma unroll
    for (int ww = 0; ww < 8; ww++) {
        scl[ww] = __expf(pms[ww * 2] - Mg);
        Sg += pms[ww * 2 + 1] * scl[ww];
    }
    float inv = 1.f / Sg;
    for (int h = tid; h < HH; h += 256) {
        float a = 0.f;
#pragma unroll
        for (int ww = 0; ww < 8; ww++) a += pa[ww * 512 + h] * scl[ww];
        g_ctx[(size_t)b * HH + h] = __float2half(a * inv);
    }
    __syncthreads();
}

__global__ void __launch_bounds__(256, 1) dec_persistent(
    const float* __restrict__ Wdi, const float* __restrict__ Wdh,
    const float* __restrict__ bdi, const float* __restrict__ bdh,
    const float* __restrict__ Wfc, const float* __restrict__ bfc,
    float* __restrict__ out) {
    extern __shared__ __half smh[];
    __half* Ws = smh;
    __half* As = smh + 33024;
    float* fb  = (float*)(smh + 33024 + 18432);
    float* pa   = fb;
    float* pms  = fb + 4096;
    float* bias = fb + 4112;
    float* wd0  = fb + 4144;

    int bx = blockIdx.x, tid = threadIdx.x;
    int lane = tid & 31, wid = tid >> 5;
    int lr = lane >> 2, lc = lane & 3, lc2 = lc * 2;
    int wm = wid >> 1, wn = wid & 1;
    int mh = bx & 1;
    int nbase = (bx >> 1) * 8;

    for (int cc = wid; cc < 32; cc += 8) {
        int gq = (cc & 1) | ((cc >> 2) & 2);
        int dn = ((cc >> 1) & 3) | ((cc >> 4) << 2);
        int row = gq * HH + nbase + dn;
        for (int k = lane; k < HH; k += 32) {
            Ws[(size_t)cc * 1032 + k]      = __float2half(Wdi[(size_t)row * (HH + 1) + 1 + k]);
            Ws[(size_t)cc * 1032 + HH + k] = __float2half(Wdh[(size_t)row * HH + k]);
        }
        if (lane == 0) {
            bias[cc] = bdi[row] + bdh[row];
            wd0[cc]  = Wdi[(size_t)row * (HH + 1)];
        }
    }
    float cst[2][2];
#pragma unroll
    for (int mi = 0; mi < 2; mi++)
#pragma unroll
        for (int rh = 0; rh < 2; rh++) {
            int b = mh * 128 + wm * 32 + mi * 16 + rh * 8 + lr;
            int n = nbase + lc + 4 * wn;
            cst[mi][rh] = g_c1f[(size_t)b * HH + n];
        }
    __syncthreads();

    unsigned round = 0;
    for (int ds = 0; ds <= PL; ds++) {
        attn_one(ds, bx, ds < PL, Wfc, bfc, out, pa, pms);
        attn_one(ds, bx + 128, ds < PL, Wfc, bfc, out, pa, pms);
        if (ds == PL) break;
        gridbar(&g_bar_dec, round, NBD);

        float acc[2][2][4];
#pragma unroll
        for (int a = 0; a < 2; a++)
#pragma unroll
            for (int b = 0; b < 2; b++)
#pragma unroll
                for (int q = 0; q < 4; q++) acc[a][b][q] = 0.f;
        gemm16<2, 16, 1032>(g_ctx + (size_t)mh * 128 * HH,
                            g_h1[ds & 1] + (size_t)mh * 128 * HH,
                            As, Ws, acc, wm, wn, lr, lc2);
        __half* h1n = g_h1[(ds + 1) & 1];
#pragma unroll
        for (int mi = 0; mi < 2; mi++)
#pragma unroll
            for (int rh = 0; rh < 2; rh++) {
                int b = mh * 128 + wm * 32 + mi * 16 + rh * 8 + lr;
                float y = g_yprev[b];
                int n = nbase + lc + 4 * wn;
                float gv[4];
#pragma unroll
                for (int gq = 0; gq < 4; gq++) {
                    int ni = gq >> 1;
                    int cc = wn * 16 + ni * 8 + lc2 + (gq & 1);
                    gv[gq] = acc[mi][ni][rh * 2 + (gq & 1)] + bias[cc] + wd0[cc] * y;
                }
                float ig = sigf(gv[0]), fg = sigf(gv[1]);
                float gg = tanhf(gv[2]), og = sigf(gv[3]);
                float cv = fg * cst[mi][rh] + ig * gg;
                cst[mi][rh] = cv;
                h1n[(size_t)b * HH + n] = __float2half(og * tanhf(cv));
            }
        gridbar(&g_bar_dec, round, NBD);
    }
}

extern "C" void kernel_launch(void* const* d_in, const int* in_sizes, int n_in,
                              void* d_out, int out_size) {
    const float* x    = (const float*)d_in[0];
    const float* Wih0 = (const float*)d_in[1];
    const float* Whh0 = (const float*)d_in[2];
    const float* bi0  = (const float*)d_in[3];
    const float* bh0  = (const float*)d_in[4];
    const float* Wih1 = (const float*)d_in[5];
    const float* Whh1 = (const float*)d_in[6];
    const float* bi1  = (const float*)d_in[7];
    const float* bh1  = (const float*)d_in[8];
    const float* Wdi  = (const float*)d_in[9];
    const float* Wdh  = (const float*)d_in[10];
    const float* bdi  = (const float*)d_in[11];
    const float* bdh  = (const float*)d_in[12];
    const float* Wfc  = (const float*)d_in[13];
    const float* bfc  = (const float*)d_in[14];
    float* out = (float*)d_out;

    cudaFuncSetAttribute(enc_persistent, cudaFuncAttributeMaxDynamicSharedMemorySize, ENC_SMEM);
    cudaFuncSetAttribute(dec_persistent, cudaFuncAttributeMaxDynamicSharedMemorySize, 119616);

    prep_kernel<<<(BB * HH + 255) / 256, 256>>>();
    xp_kernel<<<dim3(LL, 8), 256>>>(x, Wih0, bi0, bh0);
    enc_persistent<<<NBE, 256, ENC_SMEM>>>(Whh0, Wih1, Whh1, bi1, bh1);
    dec_persistent<<<NBD, 256, 119616>>>(Wdi, Wdh, bdi, bdh, Wfc, bfc, out);
}

// round 8
// speedup vs baseline: 1.3147x; 1.3147x over previous
#include <cuda_runtime.h>
#include <cuda_fp16.h>
#include <stdint.h>

#define BB 256
#define LL 336
#define NIN 8
#define HH 512
#define PL 96
#define NBE 96
#define NBD 128

// chunked h layout: [mh*8+kc] chunks of 8192 halves; within chunk:
// elem(row,klocal) at ((klocal>>3)*128 + row)*8 + (klocal&7)
__device__ __align__(128) __half g_h0[2][BB*HH];
__device__ __align__(128) __half g_h1[2][BB*HH];
__device__ __align__(128) __half g_ctxc[BB*HH];
__device__ float  g_c1f[BB*HH];
__device__ float  g_yprev[BB];
__device__ __align__(128) __half g_enc[(size_t)LL*BB*HH];     // standard [l][b][n]
__device__ __align__(128) __half g_xp[(size_t)LL*32*16384];   // [s][cta][row][nl][4]
__device__ unsigned g_bar_enc, g_bar_dec;

__device__ __forceinline__ float sigf(float x) { return 1.f / (1.f + __expf(-x)); }

__device__ __forceinline__ void gridbar(unsigned* bar, unsigned& round, unsigned nblk) {
    round++;
    __syncthreads();
    __threadfence();
    if (threadIdx.x == 0) {
        unsigned target = round * nblk;
        atomicAdd(bar, 1u);
        while (*(volatile unsigned*)bar < target) { }
        __threadfence();
    }
    __syncthreads();
}

__device__ __forceinline__ uint32_t smem_u32(const void* p) {
    uint32_t a;
    asm("{ .reg .u64 t; cvta.to.shared.u64 t, %1; cvt.u32.u64 %0, t; }" : "=r"(a) : "l"(p));
    return a;
}
__device__ __forceinline__ void mma16(float c[4], const uint32_t a[4], const uint32_t b[2]) {
    asm volatile(
        "mma.sync.aligned.m16n8k16.row.col.f32.f16.f16.f32 "
        "{%0,%1,%2,%3},{%4,%5,%6,%7},{%8,%9},{%0,%1,%2,%3};"
        : "+f"(c[0]), "+f"(c[1]), "+f"(c[2]), "+f"(c[3])
        : "r"(a[0]), "r"(a[1]), "r"(a[2]), "r"(a[3]), "r"(b[0]), "r"(b[1]));
}
#define LDSM4(r0, r1, r2, r3, addr) \
    asm volatile("ldmatrix.sync.aligned.m8n8.x4.shared.b16 {%0,%1,%2,%3},[%4];" \
                 : "=r"(r0), "=r"(r1), "=r"(r2), "=r"(r3) : "r"(addr))

__device__ __forceinline__ void mbar_init(uint32_t mbar, uint32_t cnt) {
    asm volatile("mbarrier.init.shared.b64 [%0], %1;" :: "r"(mbar), "r"(cnt) : "memory");
}
__device__ __forceinline__ void mbar_wait(uint32_t mbar, uint32_t parity) {
    uint32_t done = 0;
    while (!done) {
        asm volatile(
            "{\n\t.reg .pred p;\n\t"
            "mbarrier.try_wait.parity.acquire.cta.shared::cta.b64 p, [%1], %2, 0x989680;\n\t"
            "selp.b32 %0, 1, 0, p;\n\t}"
            : "=r"(done) : "r"(mbar), "r"(parity) : "memory");
    }
}
__device__ __forceinline__ void issue_bulk(uint32_t dst, const void* src, uint32_t bytes,
                                           uint32_t mbar) {
    asm volatile("mbarrier.arrive.expect_tx.shared.b64 _, [%0], %1;"
                 :: "r"(mbar), "r"(bytes) : "memory");
    asm volatile(
        "cp.async.bulk.shared::cluster.global.mbarrier::complete_tx::bytes [%0], [%1], %2, [%3];"
        :: "r"(dst), "l"(src), "r"(bytes), "r"(mbar) : "memory");
}

// ---- one 64-k chunk of mma: A from bulk-staged chunk buffer, B from padded weights ----
template<int NQ, int KPAD>
__device__ __forceinline__ void mma_chunk(uint32_t abuf, uint32_t wsm, int kglob,
                                          float (&acc)[2][NQ*2][4],
                                          uint32_t albase, int bcol, int bkh) {
#pragma unroll
    for (int j = 0; j < 4; j++) {
        uint32_t a[2][4];
#pragma unroll
        for (int mi = 0; mi < 2; mi++)
            LDSM4(a[mi][0], a[mi][1], a[mi][2], a[mi][3],
                  abuf + albase + j * 4096 + mi * 256);
#pragma unroll
        for (int q = 0; q < NQ; q++) {
            uint32_t b[4];
            LDSM4(b[0], b[1], b[2], b[3],
                  wsm + (uint32_t)((bcol + q * 32) * KPAD + kglob + j * 16 + bkh) * 2);
#pragma unroll
            for (int mi = 0; mi < 2; mi++) {
                mma16(acc[mi][q * 2 + 0], a[mi], b);
                mma16(acc[mi][q * 2 + 1], a[mi], b + 2);
            }
        }
    }
}

// ---- bulk-staged K loop ----
template<int NCH, int NQ, int KPAD>
__device__ __forceinline__ void gemm_run(const __half* p0, const __half* p1,
                                         uint32_t wsm, uint32_t ab0, uint32_t ab1,
                                         uint32_t mb0, uint32_t mb1,
                                         float (&acc)[2][NQ*2][4],
                                         unsigned& c0, unsigned& c1,
                                         uint32_t albase, int bcol, int bkh, int tid) {
    if (tid == 0) {
        issue_bulk(ab0, p0, 16384, mb0);
        if (NCH > 1) {
            const __half* s1 = (1 < 8 || p1 == nullptr) ? p0 + 8192 : p1;
            issue_bulk(ab1, s1, 16384, mb1);
        }
    }
    for (int kc = 0; kc < NCH; kc++) {
        uint32_t mb = (kc & 1) ? mb1 : mb0;
        uint32_t ab = (kc & 1) ? ab1 : ab0;
        unsigned& cc = (kc & 1) ? c1 : c0;
        mbar_wait(mb, cc & 1);
        cc++;
        mma_chunk<NQ, KPAD>(ab, wsm, kc * 64, acc, albase, bcol, bkh);
        __syncthreads();
        if (tid == 0 && kc + 2 < NCH) {
            int nk = kc + 2;
            const __half* s = (nk < 8 || p1 == nullptr) ? p0 + (size_t)nk * 8192
                                                        : p1 + (size_t)(nk - 8) * 8192;
            issue_bulk(ab, s, 16384, mb);
        }
    }
}

// ---------------- prep + xp ----------------
__global__ void prep_kernel() {
    int i = blockIdx.x * blockDim.x + threadIdx.x;
    if (i < BB * HH) {
        g_h0[0][i] = __float2half(0.f);
        g_h1[0][i] = __float2half(0.f);
    }
    if (i == 0) { g_bar_enc = 0u; g_bar_dec = 0u; }
}

// g_xp[s][c][row][nl][4]: gate-quad (i,f,g,o) of x@Wih0 + b for L0 CTA c's 32 n
__global__ void xp_kernel(const float* __restrict__ x, const float* __restrict__ Wih0,
                          const float* __restrict__ bi0, const float* __restrict__ bh0) {
    int s = blockIdx.x, c = blockIdx.y, tid = threadIdx.x;
    int mh = c & 1, nbq = c >> 1;
    __shared__ float xs[128 * 8];
    __shared__ float Wq[32 * 4 * 8];
    __shared__ float bq[32 * 4];
    for (int idx = tid; idx < 1024; idx += 256) {
        int bl = idx >> 3, k = idx & 7;
        xs[idx] = x[((size_t)(mh * 128 + bl) * LL + s) * NIN + k];
    }
    for (int idx = tid; idx < 1024; idx += 256) {
        int nl = idx >> 5, g = (idx >> 3) & 3, k = idx & 7;
        int row = g * HH + nbq * 32 + nl;
        Wq[idx] = Wih0[row * NIN + k];
    }
    if (tid < 128) {
        int nl = tid >> 2, g = tid & 3;
        int row = g * HH + nbq * 32 + nl;
        bq[tid] = bi0[row] + bh0[row];
    }
    __syncthreads();
    int bl = tid & 127, half = tid >> 7;
    __half* dst = g_xp + ((size_t)s * 32 + c) * 16384 + (size_t)bl * 128 + half * 64;
    const float* xr = xs + bl * 8;
    for (int u = 0; u < 16; u++) {
        int nl = half * 16 + u;
        __half q4[4];
#pragma unroll
        for (int g = 0; g < 4; g++) {
            const float* wr = Wq + (nl * 4 + g) * 8;
            float a = bq[nl * 4 + g];
#pragma unroll
            for (int k = 0; k < 8; k++) a += wr[k] * xr[k];
            q4[g] = __float2half(a);
        }
        *(uint2*)(dst + u * 4) = *(uint2*)q4;
    }
}

// ---------------- ENCODER ----------------
#define OF_AB0  133120
#define OF_AB1  149504
#define OF_XP   165888
#define OF_HT   198656
#define OF_BIAS 206848
#define OF_MBAR 207104
#define ENC_SMEM 207360

__global__ void __launch_bounds__(256, 1) enc_persistent(
    const float* __restrict__ Whh0, const float* __restrict__ Wih1,
    const float* __restrict__ Whh1,
    const float* __restrict__ bi1, const float* __restrict__ bh1) {
    extern __shared__ __align__(16) char smc[];
    __half* Wsm = (__half*)smc;
    __half* ht  = (__half*)(smc + OF_HT);
    float*  bq1 = (float*)(smc + OF_BIAS);
    uint32_t smb = smem_u32(smc);

    int bx = blockIdx.x, tid = threadIdx.x;
    int lane = tid & 31, wid = tid >> 5;
    int wm = wid >> 1, wn = wid & 1;
    int i4 = lane >> 3, r8 = lane & 7;
    int er = lane >> 2, ec = lane & 3;
    bool L0 = bx < 32;
    int cid = L0 ? bx : bx - 32;
    int mh = cid & 1, nbq = cid >> 1;

    // ---- weights to smem ----
    if (L0) {
        for (int idx = tid; idx < 128 * 128; idx += 256) {
            int cc = idx >> 7, k4 = (idx & 127) * 4;
            int q = cc >> 5, r5 = cc & 31;
            int gate = (r5 & 1) | (((r5 >> 3) & 1) << 1);
            int n = nbq * 32 + q * 8 + ((r5 >> 4) & 1) * 4 + ((r5 >> 1) & 3);
            float4 w = *(const float4*)(Whh0 + (size_t)(gate * HH + n) * HH + k4);
            __half* d = Wsm + (size_t)cc * 520 + k4;
            d[0] = __float2half(w.x); d[1] = __float2half(w.y);
            d[2] = __float2half(w.z); d[3] = __float2half(w.w);
        }
    } else {
        for (int idx = tid; idx < 64 * 256; idx += 256) {
            int cc = idx >> 8, k4 = (idx & 255) * 4;
            int q = cc >> 5, r5 = cc & 31;
            int gate = (r5 & 1) | (((r5 >> 3) & 1) << 1);
            int n = nbq * 16 + q * 8 + ((r5 >> 4) & 1) * 4 + ((r5 >> 1) & 3);
            int row = gate * HH + n;
            const float* srcW = (k4 < HH) ? Wih1 + (size_t)row * HH + k4
                                          : Whh1 + (size_t)row * HH + (k4 - HH);
            float4 w = *(const float4*)srcW;
            __half* d = Wsm + (size_t)cc * 1032 + k4;
            d[0] = __float2half(w.x); d[1] = __float2half(w.y);
            d[2] = __float2half(w.z); d[3] = __float2half(w.w);
        }
        if (tid < 64) {
            int nl = tid >> 2, g = tid & 3;
            int n = nbq * 16 + nl;
            bq1[tid] = bi1[g * HH + n] + bh1[g * HH + n];
        }
    }
    if (tid == 0) {
        mbar_init(smb + OF_MBAR, 1);
        mbar_init(smb + OF_MBAR + 8, 1);
        mbar_init(smb + OF_MBAR + 16, 1);
    }
    __syncthreads();

    uint32_t albase = ((uint32_t)((i4 >> 1) & 1)) * 2048 +
                      (uint32_t)(wm * 32 + (i4 & 1) * 8 + r8) * 16;
    int bcol = wn * 16 + ((i4 >> 1) & 1) * 8 + r8;
    int bkh = (i4 & 1) * 8;

    float cst[16];
#pragma unroll
    for (int i = 0; i < 16; i++) cst[i] = 0.f;

    unsigned cA0 = 0, cA1 = 0, cXP = 0;
    unsigned round = 0;
    for (int s = 0; s <= LL; s++) {
        bool act = L0 ? (s < LL) : (s >= 1);
        if (act) {
            if (L0) {
                if (tid == 0)
                    issue_bulk(smb + OF_XP, g_xp + ((size_t)s * 32 + bx) * 16384, 32768,
                               smb + OF_MBAR + 16);
                float acc[2][8][4];
#pragma unroll
                for (int a = 0; a < 2; a++)
#pragma unroll
                    for (int b = 0; b < 8; b++)
#pragma unroll
                        for (int qd = 0; qd < 4; qd++) acc[a][b][qd] = 0.f;
                const __half* p0 = g_h0[s & 1] + (size_t)mh * 8 * 8192;
                gemm_run<8, 4, 520>(p0, nullptr, smb, smb + OF_AB0, smb + OF_AB1,
                                    smb + OF_MBAR, smb + OF_MBAR + 8,
                                    acc, cA0, cA1, albase, bcol, bkh, tid);
                mbar_wait(smb + OF_MBAR + 16, cXP & 1);
                cXP++;
                const __half* xpb = (const __half*)(smc + OF_XP);
#pragma unroll
                for (int q = 0; q < 4; q++)
#pragma unroll
                    for (int mi = 0; mi < 2; mi++)
#pragma unroll
                        for (int rh = 0; rh < 2; rh++) {
                            int row = wm * 32 + mi * 16 + rh * 8 + er;
                            int nl = q * 8 + wn * 4 + ec;
                            uint2 xu = *(const uint2*)(xpb + (size_t)(row * 32 + nl) * 4);
                            const __half* xh = (const __half*)&xu;
                            float g0 = acc[mi][q * 2 + 0][rh * 2]     + __half2float(xh[0]);
                            float g1 = acc[mi][q * 2 + 0][rh * 2 + 1] + __half2float(xh[1]);
                            float g2 = acc[mi][q * 2 + 1][rh * 2]     + __half2float(xh[2]);
                            float g3 = acc[mi][q * 2 + 1][rh * 2 + 1] + __half2float(xh[3]);
                            float ig = sigf(g0), fg = sigf(g1);
                            float gg = tanhf(g2), og = sigf(g3);
                            int ix = (q * 2 + mi) * 2 + rh;
                            float cv = fg * cst[ix] + ig * gg;
                            cst[ix] = cv;
                            ht[row * 32 + nl] = __float2half(og * tanhf(cv));
                        }
                __syncthreads();
                {   // write h0 next buf, chunked layout
                    int row = tid & 127, part = tid >> 7;
                    __half* hb = g_h0[(s + 1) & 1];
#pragma unroll
                    for (int u = 0; u < 2; u++) {
                        int nl0 = part * 16 + u * 8;
                        int kc = nbq >> 1;
                        int seg = (nbq & 1) * 4 + part * 2 + u;
                        uint4 v = *(uint4*)(ht + row * 32 + nl0);
                        *(uint4*)(hb + (size_t)(mh * 8 + kc) * 8192 +
                                  (size_t)(seg * 128 + row) * 8) = v;
                    }
                }
            } else {
                float acc[2][4][4];
#pragma unroll
                for (int a = 0; a < 2; a++)
#pragma unroll
                    for (int b = 0; b < 4; b++)
#pragma unroll
                        for (int qd = 0; qd < 4; qd++) acc[a][b][qd] = 0.f;
                const __half* p0 = g_h0[s & 1] + (size_t)mh * 8 * 8192;
                const __half* p1 = g_h1[(s + 1) & 1] + (size_t)mh * 8 * 8192;
                gemm_run<16, 2, 1032>(p0, p1, smb, smb + OF_AB0, smb + OF_AB1,
                                      smb + OF_MBAR, smb + OF_MBAR + 8,
                                      acc, cA0, cA1, albase, bcol, bkh, tid);
#pragma unroll
                for (int q = 0; q < 2; q++)
#pragma unroll
                    for (int mi = 0; mi < 2; mi++)
#pragma unroll
                        for (int rh = 0; rh < 2; rh++) {
                            int row = wm * 32 + mi * 16 + rh * 8 + er;
                            int nl = q * 8 + wn * 4 + ec;
                            const float* bqp = bq1 + nl * 4;
                            float g0 = acc[mi][q * 2 + 0][rh * 2]     + bqp[0];
                            float g1 = acc[mi][q * 2 + 0][rh * 2 + 1] + bqp[1];
                            float g2 = acc[mi][q * 2 + 1][rh * 2]     + bqp[2];
                            float g3 = acc[mi][q * 2 + 1][rh * 2 + 1] + bqp[3];
                            float ig = sigf(g0), fg = sigf(g1);
                            float gg = tanhf(g2), og = sigf(g3);
                            int ix = (q * 2 + mi) * 2 + rh;
                            float cv = fg * cst[ix] + ig * gg;
                            cst[ix] = cv;
                            ht[row * 16 + nl] = __float2half(og * tanhf(cv));
                            if (s == LL)
                                g_c1f[(size_t)(mh * 128 + row) * HH + nbq * 16 + nl] = cv;
                        }
                __syncthreads();
                {
                    int row = tid & 127, part = tid >> 7;
                    int nl0 = part * 8;
                    int kc = nbq >> 2;
                    int seg = (nbq & 3) * 2 + part;
                    uint4 v = *(uint4*)(ht + row * 16 + nl0);
                    *(uint4*)(g_h1[s & 1] + (size_t)(mh * 8 + kc) * 8192 +
                              (size_t)(seg * 128 + row) * 8) = v;
                    *(uint4*)(g_enc + (size_t)(s - 1) * BB * HH +
                              (size_t)(mh * 128 + row) * HH + nbq * 16 + nl0) = v;
                }
            }
        }
        gridbar(&g_bar_enc, round, NBE);
    }
}

// ---------------- DECODER ----------------
#define DOF_AB0  66048
#define DOF_AB1  82432
#define DOF_PA   98816
#define DOF_PMS  115200
#define DOF_BQ   115264
#define DOF_WD0  115392
#define DOF_MBAR 115520
#define DEC_SMEM 115584

__device__ __forceinline__ float dot8r(uint4 v, const float* s) {
    const __half2* h2 = (const __half2*)&v;
    float r = 0.f;
#pragma unroll
    for (int i = 0; i < 4; i++) {
        float2 f = __half22float2(h2[i]);
        r += f.x * s[2 * i] + f.y * s[2 * i + 1];
    }
    return r;
}

__device__ void attn_one(int ds, int b, bool full, const float* __restrict__ Wfc,
                         const float* __restrict__ bfc, float* __restrict__ out,
                         float* pa, float* pms) {
    int tid = threadIdx.x, lane = tid & 31, w = tid >> 5;
    int mhB = b >> 7, rowB = b & 127;
    const __half* h1b = g_h1[ds & 1];
    uint4 hv0 = *(const uint4*)(h1b + (size_t)(mhB * 8 + (lane >> 3)) * 8192 +
                                (size_t)((lane & 7) * 128 + rowB) * 8);
    uint4 hv1 = *(const uint4*)(h1b + (size_t)(mhB * 8 + 4 + (lane >> 3)) * 8192 +
                                (size_t)((lane & 7) * 128 + rowB) * 8);
    float hreg[16];
    {
        const __half* ha = (const __half*)&hv0;
        const __half* hb = (const __half*)&hv1;
#pragma unroll
        for (int i = 0; i < 8; i++) {
            hreg[i]     = __half2float(ha[i]);
            hreg[8 + i] = __half2float(hb[i]);
        }
    }
    if (w == 0) {
        float yv = 0.f;
#pragma unroll
        for (int i = 0; i < 8; i++)
            yv += hreg[i] * Wfc[lane * 8 + i] + hreg[8 + i] * Wfc[256 + lane * 8 + i];
#pragma unroll
        for (int off = 16; off; off >>= 1) yv += __shfl_xor_sync(0xffffffffu, yv, off);
        if (lane == 0) {
            float y = yv + bfc[0];
            if (ds > 0) out[b * PL + ds - 1] = y;
            g_yprev[b] = (ds == 0) ? 0.f : y;
        }
    }
    if (!full) return;

    float M = -1e30f, S = 0.f, C[16];
#pragma unroll
    for (int i = 0; i < 16; i++) C[i] = 0.f;
    for (int l = w; l < LL; l += 8) {
        const uint4* e4 = (const uint4*)(g_enc + ((size_t)l * BB + b) * HH);
        uint4 v0 = e4[lane];
        uint4 v1 = e4[lane + 32];
        float s1 = dot8r(v0, hreg) + dot8r(v1, hreg + 8);
#pragma unroll
        for (int off = 16; off; off >>= 1) s1 += __shfl_xor_sync(0xffffffffu, s1, off);
        float mn = fmaxf(M, s1);
        float r = __expf(M - mn);
        float e = __expf(s1 - mn);
        S = S * r + e;
        const __half2* ha = (const __half2*)&v0;
        const __half2* hb = (const __half2*)&v1;
#pragma unroll
        for (int i = 0; i < 4; i++) {
            float2 f = __half22float2(ha[i]);
            C[2 * i]     = C[2 * i] * r + e * f.x;
            C[2 * i + 1] = C[2 * i + 1] * r + e * f.y;
            float2 f2 = __half22float2(hb[i]);
            C[8 + 2 * i]     = C[8 + 2 * i] * r + e * f2.x;
            C[8 + 2 * i + 1] = C[8 + 2 * i + 1] * r + e * f2.y;
        }
        M = mn;
    }
    if (lane == 0) { pms[w * 2] = M; pms[w * 2 + 1] = S; }
#pragma unroll
    for (int i = 0; i < 8; i++) {
        pa[w * 512 + lane * 8 + i]       = C[i];
        pa[w * 512 + 256 + lane * 8 + i] = C[8 + i];
    }
    __syncthreads();
    float Mg = -1e30f;
#pragma unroll
    for (int ww = 0; ww < 8; ww++) Mg = fmaxf(Mg, pms[ww * 2]);
    float Sg = 0.f;
    float scl[8];
#pragma unroll
    for (int ww = 0; ww < 8; ww++) {
        scl[ww] = __expf(pms[ww * 2] - Mg);
        Sg += pms[ww * 2 + 1] * scl[ww];
    }
    float inv = 1.f / Sg;
    for (int h = tid; h < HH; h += 256) {
        float a = 0.f;
#pragma unroll
        for (int ww = 0; ww < 8; ww++) a += pa[ww * 512 + h] * scl[ww];
        // chunked ctx write
        g_ctxc[(size_t)(mhB * 8 + (h >> 6)) * 8192 +
               (size_t)(((h & 63) >> 3) * 128 + rowB) * 8 + (h & 7)] = __float2half(a * inv);
    }
    __syncthreads();
}

__global__ void __launch_bounds__(256, 1) dec_persistent(
    const float* __restrict__ Wdi, const float* __restrict__ Wdh,
    const float* __restrict__ bdi, const float* __restrict__ bdh,
    const float* __restrict__ Wfc, const float* __restrict__ bfc,
    float* __restrict__ out) {
    extern __shared__ __align__(16) char smc[];
    __half* Wsm = (__half*)smc;
    float* pa  = (float*)(smc + DOF_PA);
    float* pms = (float*)(smc + DOF_PMS);
    float* bqd = (float*)(smc + DOF_BQ);
    float* wd0 = (float*)(smc + DOF_WD0);
    uint32_t smb = smem_u32(smc);

    int bx = blockIdx.x, tid = threadIdx.x;
    int lane = tid & 31, wid = tid >> 5;
    int wm = wid >> 1, wn = wid & 1;
    int i4 = lane >> 3, r8 = lane & 7;
    int er = lane >> 2, ec = lane & 3;
    int mh = bx & 1;
    int nb8 = (bx >> 1) * 8;

    for (int idx = tid; idx < 32 * 256; idx += 256) {
        int cc = idx >> 8, k4 = (idx & 255) * 4;
        int gate = (cc & 1) | (((cc >> 3) & 1) << 1);
        int n = nb8 + ((cc >> 4) & 1) * 4 + ((cc >> 1) & 3);
        int row = gate * HH + n;
        float w4[4];
        if (k4 < HH) {
            const float* sp = Wdi + (size_t)row * (HH + 1) + 1 + k4;
            w4[0] = sp[0]; w4[1] = sp[1]; w4[2] = sp[2]; w4[3] = sp[3];
        } else {
            float4 wv = *(const float4*)(Wdh + (size_t)row * HH + (k4 - HH));
            w4[0] = wv.x; w4[1] = wv.y; w4[2] = wv.z; w4[3] = wv.w;
        }
        __half* d = Wsm + (size_t)cc * 1032 + k4;
        d[0] = __float2half(w4[0]); d[1] = __float2half(w4[1]);
        d[2] = __float2half(w4[2]); d[3] = __float2half(w4[3]);
    }
    if (tid < 32) {
        int nl = tid >> 2, g = tid & 3;
        int n = nb8 + nl;
        int row = g * HH + n;
        bqd[nl * 4 + g] = bdi[row] + bdh[row];
        wd0[nl * 4 + g] = Wdi[(size_t)row * (HH + 1)];
    }
    if (tid == 0) {
        mbar_init(smb + DOF_MBAR, 1);
        mbar_init(smb + DOF_MBAR + 8, 1);
    }
    __syncthreads();

    uint32_t albase = ((uint32_t)((i4 >> 1) & 1)) * 2048 +
                      (uint32_t)(wm * 32 + (i4 & 1) * 8 + r8) * 16;
    int bcol = wn * 16 + ((i4 >> 1) & 1) * 8 + r8;
    int bkh = (i4 & 1) * 8;

    float cst[4];
#pragma unroll
    for (int mi = 0; mi < 2; mi++)
#pragma unroll
        for (int rh = 0; rh < 2; rh++) {
            int b = mh * 128 + wm * 32 + mi * 16 + rh * 8 + er;
            cst[mi * 2 + rh] = g_c1f[(size_t)b * HH + nb8 + wn * 4 + ec];
        }

    unsigned cA0 = 0, cA1 = 0;
    unsigned round = 0;
    for (int ds = 0; ds <= PL; ds++) {
        attn_one(ds, bx, ds < PL, Wfc, bfc, out, pa, pms);
        attn_one(ds, bx + 128, ds < PL, Wfc, bfc, out, pa, pms);
        if (ds == PL) break;
        gridbar(&g_bar_dec, round, NBD);

        float acc[2][2][4];
#pragma unroll
        for (int a = 0; a < 2; a++)
#pragma unroll
            for (int b = 0; b < 2; b++)
#pragma unroll
                for (int qd = 0; qd < 4; qd++) acc[a][b][qd] = 0.f;
        const __half* p0 = g_ctxc + (size_t)mh * 8 * 8192;
        const __half* p1 = g_h1[ds & 1] + (size_t)mh * 8 * 8192;
        gemm_run<16, 1, 1032>(p0, p1, smb, smb + DOF_AB0, smb + DOF_AB1,
                              smb + DOF_MBAR, smb + DOF_MBAR + 8,
                              acc, cA0, cA1, albase, bcol, bkh, tid);
        {
            int nl = wn * 4 + ec;
            int n = nb8 + nl;
            int kc = n >> 6;
            int seg = (n & 63) >> 3;
            __half* hb = g_h1[(ds + 1) & 1];
#pragma unroll
            for (int mi = 0; mi < 2; mi++)
#pragma unroll
                for (int rh = 0; rh < 2; rh++) {
                    int row = wm * 32 + mi * 16 + rh * 8 + er;
                    int b = mh * 128 + row;
                    float y = g_yprev[b];
                    const float* bp = bqd + nl * 4;
                    const float* wp = wd0 + nl * 4;
                    float g0 = acc[mi][0][rh * 2]     + bp[0] + wp[0] * y;
                    float g1 = acc[mi][0][rh * 2 + 1] + bp[1] + wp[1] * y;
                    float g2 = acc[mi][1][rh * 2]     + bp[2] + wp[2] * y;
                    float g3 = acc[mi][1][rh * 2 + 1] + bp[3] + wp[3] * y;
                    float ig = sigf(g0), fg = sigf(g1);
                    float gg = tanhf(g2), og = sigf(g3);
                    float cv = fg * cst[mi * 2 + rh] + ig * gg;
                    cst[mi * 2 + rh] = cv;
                    hb[(size_t)(mh * 8 + kc) * 8192 + (size_t)(seg * 128 + row) * 8 +
                       (n & 7)] = __float2half(og * tanhf(cv));
                }
        }
        gridbar(&g_bar_dec, round, NBD);
    }
}

extern "C" void kernel_launch(void* const* d_in, const int* in_sizes, int n_in,
                              void* d_out, int out_size) {
    const float* x    = (const float*)d_in[0];
    const float* Wih0 = (const float*)d_in[1];
    const float* Whh0 = (const float*)d_in[2];
    const float* bi0  = (const float*)d_in[3];
    const float* bh0  = (const float*)d_in[4];
    const float* Wih1 = (const float*)d_in[5];
    const float* Whh1 = (const float*)d_in[6];
    const float* bi1  = (const float*)d_in[7];
    const float* bh1  = (const float*)d_in[8];
    const float* Wdi  = (const float*)d_in[9];
    const float* Wdh  = (const float*)d_in[10];
    const float* bdi  = (const float*)d_in[11];
    const float* bdh  = (const float*)d_in[12];
    const float* Wfc  = (const float*)d_in[13];
    const float* bfc  = (const float*)d_in[14];
    float* out = (float*)d_out;

    cudaFuncSetAttribute(enc_persistent, cudaFuncAttributeMaxDynamicSharedMemorySize, ENC_SMEM);
    cudaFuncSetAttribute(dec_persistent, cudaFuncAttributeMaxDynamicSharedMemorySize, DEC_SMEM);

    prep_kernel<<<(BB * HH + 255) / 256, 256>>>();
    xp_kernel<<<dim3(LL, 32), 256>>>(x, Wih0, bi0, bh0);
    enc_persistent<<<NBE, 256, ENC_SMEM>>>(Whh0, Wih1, Whh1, bi1, bh1);
    dec_persistent<<<NBD, 256, DEC_SMEM>>>(Wdi, Wdh, bdi, bdh, Wfc, bfc, out);
}

// round 9
// speedup vs baseline: 1.5971x; 1.2148x over previous
#include <cuda_runtime.h>
#include <cuda_fp16.h>
#include <stdint.h>

#define BB 256
#define LL 336
#define NIN 8
#define HH 512
#define PL 96
#define NBE 128
#define NBD 128

// chunked h layout: [mh*8+kc] chunks of 8192 halves; within chunk:
// elem(row,klocal) at ((klocal>>3)*128 + row)*8 + (klocal&7)
__device__ __align__(128) __half g_h0[2][BB*HH];
__device__ __align__(128) __half g_h1[2][BB*HH];
__device__ __align__(128) __half g_ctxc[BB*HH];
__device__ float  g_c1f[BB*HH];
__device__ float  g_yprev[BB];
__device__ __align__(128) __half g_enc[(size_t)LL*BB*HH];     // [l][b][n]
__device__ __align__(128) __half g_xp[(size_t)LL*BB*2048];    // [s][cta128][row128][nl8][4]
__device__ unsigned g_bar_enc, g_bar_dec;

__device__ __forceinline__ float sigf(float x) { return 1.f / (1.f + __expf(-x)); }

__device__ __forceinline__ void gridbar(unsigned* bar, unsigned& round, unsigned nblk) {
    round++;
    __syncthreads();
    __threadfence();
    if (threadIdx.x == 0) {
        unsigned target = round * nblk;
        atomicAdd(bar, 1u);
        while (*(volatile unsigned*)bar < target) { }
        __threadfence();
    }
    __syncthreads();
}

__device__ __forceinline__ uint32_t smem_u32(const void* p) {
    uint32_t a;
    asm("{ .reg .u64 t; cvta.to.shared.u64 t, %1; cvt.u32.u64 %0, t; }" : "=r"(a) : "l"(p));
    return a;
}
__device__ __forceinline__ void mma16(float c[4], const uint32_t a[4], const uint32_t b[2]) {
    asm volatile(
        "mma.sync.aligned.m16n8k16.row.col.f32.f16.f16.f32 "
        "{%0,%1,%2,%3},{%4,%5,%6,%7},{%8,%9},{%0,%1,%2,%3};"
        : "+f"(c[0]), "+f"(c[1]), "+f"(c[2]), "+f"(c[3])
        : "r"(a[0]), "r"(a[1]), "r"(a[2]), "r"(a[3]), "r"(b[0]), "r"(b[1]));
}
#define LDSM4(r0, r1, r2, r3, addr) \
    asm volatile("ldmatrix.sync.aligned.m8n8.x4.shared.b16 {%0,%1,%2,%3},[%4];" \
                 : "=r"(r0), "=r"(r1), "=r"(r2), "=r"(r3) : "r"(addr))

__device__ __forceinline__ void mbar_init(uint32_t mbar, uint32_t cnt) {
    asm volatile("mbarrier.init.shared.b64 [%0], %1;" :: "r"(mbar), "r"(cnt) : "memory");
}
__device__ __forceinline__ void mbar_wait(uint32_t mbar, uint32_t parity) {
    uint32_t done = 0;
    while (!done) {
        asm volatile(
            "{\n\t.reg .pred p;\n\t"
            "mbarrier.try_wait.parity.acquire.cta.shared::cta.b64 p, [%1], %2, 0x989680;\n\t"
            "selp.b32 %0, 1, 0, p;\n\t}"
            : "=r"(done) : "r"(mbar), "r"(parity) : "memory");
    }
}
__device__ __forceinline__ void issue_bulk(uint32_t dst, const void* src, uint32_t bytes,
                                           uint32_t mbar) {
    asm volatile("mbarrier.arrive.expect_tx.shared.b64 _, [%0], %1;"
                 :: "r"(mbar), "r"(bytes) : "memory");
    asm volatile(
        "cp.async.bulk.shared::cluster.global.mbarrier::complete_tx::bytes [%0], [%1], %2, [%3];"
        :: "r"(dst), "l"(src), "r"(bytes), "r"(mbar) : "memory");
}

// ---------------- prep + xp ----------------
__global__ void prep_kernel() {
    int i = blockIdx.x * blockDim.x + threadIdx.x;
    if (i < BB * HH) {
        g_h0[0][i] = __float2half(0.f);
        g_h1[0][i] = __float2half(0.f);
    }
    if (i == 0) { g_bar_enc = 0u; g_bar_dec = 0u; }
}

// g_xp[s][c][row][nl][4]: gate-quad (i,f,g,o) of x@Wih0 + b; c = mh | nb<<1, 8 hidden per c
__global__ void xp_kernel(const float* __restrict__ x, const float* __restrict__ Wih0,
                          const float* __restrict__ bi0, const float* __restrict__ bh0) {
    int s = blockIdx.x, c = blockIdx.y, tid = threadIdx.x;
    int mh = c & 1, nb = c >> 1;
    __shared__ float xs[128 * 8];
    __shared__ float Wq[8 * 4 * 8];
    __shared__ float bq[32];
    for (int idx = tid; idx < 1024; idx += 256) {
        int bl = idx >> 3, k = idx & 7;
        xs[idx] = x[((size_t)(mh * 128 + bl) * LL + s) * NIN + k];
    }
    if (tid < 256) {
        int nl = tid >> 5, g = (tid >> 3) & 3, k = tid & 7;
        Wq[tid] = Wih0[(g * HH + nb * 8 + nl) * NIN + k];
    }
    if (tid < 32) {
        int nl = tid >> 2, g = tid & 3;
        bq[tid] = bi0[g * HH + nb * 8 + nl] + bh0[g * HH + nb * 8 + nl];
    }
    __syncthreads();
    int row = tid & 127, part = tid >> 7;
    const float* xr = xs + row * 8;
    __half q16[16];
#pragma unroll
    for (int u = 0; u < 4; u++) {
        int nl = part * 4 + u;
#pragma unroll
        for (int g = 0; g < 4; g++) {
            const float* wr = Wq + (nl * 4 + g) * 8;
            float a = bq[nl * 4 + g];
#pragma unroll
            for (int k = 0; k < 8; k++) a += wr[k] * xr[k];
            q16[u * 4 + g] = __float2half(a);
        }
    }
    __half* dst = g_xp + ((size_t)s * 128 + c) * 4096 + row * 32 + part * 16;
    *(uint4*)(dst)     = *(uint4*)(q16);
    *(uint4*)(dst + 8) = *(uint4*)(q16 + 8);
}

// ---------------- ENCODER: unified 128 CTAs ----------------
// smem: WL0 33280 | WL1 66048 | AB0 16384 | AB1 16384 | XP 8192 | HT0 2048 | HT1 2048 |
//       bias1 128 | mbar 24
#define OF_WL1  33280
#define OF_AB0  99328
#define OF_AB1  115712
#define OF_XP   132096
#define OF_HT0  140288
#define OF_HT1  142336
#define OF_B1   144384
#define OF_MBAR 144512
#define ENC_SMEM 144640

__global__ void __launch_bounds__(256, 1) enc_persistent(
    const float* __restrict__ Whh0, const float* __restrict__ Wih1,
    const float* __restrict__ Whh1,
    const float* __restrict__ bi1, const float* __restrict__ bh1) {
    extern __shared__ __align__(16) char smc[];
    __half* WL0 = (__half*)smc;
    __half* WL1 = (__half*)(smc + OF_WL1);
    __half* ht0 = (__half*)(smc + OF_HT0);
    __half* ht1 = (__half*)(smc + OF_HT1);
    float*  bq1 = (float*)(smc + OF_B1);
    uint32_t smb = smem_u32(smc);

    int bx = blockIdx.x, tid = threadIdx.x;
    int lane = tid & 31, wid = tid >> 5;
    int wm = wid >> 1, wn = wid & 1;
    int i4 = lane >> 3, r8 = lane & 7;
    int er = lane >> 2, ec = lane & 3;
    int mh = bx & 1, nb = bx >> 1;   // 8 hidden units nb*8..+8, both layers

    // ---- weights to smem (32 cols, gate-permuted) ----
    for (int idx = tid; idx < 32 * 128; idx += 256) {
        int cc = idx >> 7, k4 = (idx & 127) * 4;
        int gate = (cc & 1) | (((cc >> 3) & 1) << 1);
        int n = nb * 8 + ((cc >> 4) & 1) * 4 + ((cc >> 1) & 3);
        float4 w = *(const float4*)(Whh0 + (size_t)(gate * HH + n) * HH + k4);
        __half* d = WL0 + (size_t)cc * 520 + k4;
        d[0] = __float2half(w.x); d[1] = __float2half(w.y);
        d[2] = __float2half(w.z); d[3] = __float2half(w.w);
    }
    for (int idx = tid; idx < 32 * 256; idx += 256) {
        int cc = idx >> 8, k4 = (idx & 255) * 4;
        int gate = (cc & 1) | (((cc >> 3) & 1) << 1);
        int n = nb * 8 + ((cc >> 4) & 1) * 4 + ((cc >> 1) & 3);
        int row = gate * HH + n;
        const float* srcW = (k4 < HH) ? Wih1 + (size_t)row * HH + k4
                                      : Whh1 + (size_t)row * HH + (k4 - HH);
        float4 w = *(const float4*)srcW;
        __half* d = WL1 + (size_t)cc * 1032 + k4;
        d[0] = __float2half(w.x); d[1] = __float2half(w.y);
        d[2] = __float2half(w.z); d[3] = __float2half(w.w);
    }
    if (tid < 32) {
        int nl = tid >> 2, g = tid & 3;
        int n = nb * 8 + nl;
        bq1[tid] = bi1[g * HH + n] + bh1[g * HH + n];
    }
    if (tid == 0) {
        mbar_init(smb + OF_MBAR, 1);
        mbar_init(smb + OF_MBAR + 8, 1);
        mbar_init(smb + OF_MBAR + 16, 1);
    }
    __syncthreads();

    uint32_t albase = ((uint32_t)((i4 >> 1) & 1)) * 2048 +
                      (uint32_t)(wm * 32 + (i4 & 1) * 8 + r8) * 16;
    int bcol = wn * 16 + ((i4 >> 1) & 1) * 8 + r8;
    int bkh = (i4 & 1) * 8;
    uint32_t bo0 = smb + (uint32_t)(bcol * 520 + bkh) * 2;
    uint32_t bo1 = smb + OF_WL1 + (uint32_t)(bcol * 1032 + bkh) * 2;

    float cst0[4], cst1[4];
#pragma unroll
    for (int i = 0; i < 4; i++) { cst0[i] = 0.f; cst1[i] = 0.f; }

    unsigned cA0 = 0, cA1 = 0, cXP = 0;
    unsigned round = 0;
    for (int s = 0; s <= LL; s++) {
        bool doL0 = (s < LL), doL1 = (s >= 1);
        int nch = doL1 ? 16 : 8;
        const __half* p0 = g_h0[s & 1] + (size_t)mh * 8 * 8192;
        const __half* p1 = g_h1[(s + 1) & 1] + (size_t)mh * 8 * 8192;

        if (tid == 0) {
            if (doL0)
                issue_bulk(smb + OF_XP, g_xp + ((size_t)s * 128 + bx) * 4096, 8192,
                           smb + OF_MBAR + 16);
            issue_bulk(smb + OF_AB0, p0, 16384, smb + OF_MBAR);
            issue_bulk(smb + OF_AB1, p0 + 8192, 16384, smb + OF_MBAR + 8);
        }

        float aL0[2][2][4], aL1[2][2][4];
#pragma unroll
        for (int a = 0; a < 2; a++)
#pragma unroll
            for (int b = 0; b < 2; b++)
#pragma unroll
                for (int q = 0; q < 4; q++) { aL0[a][b][q] = 0.f; aL1[a][b][q] = 0.f; }

        for (int kc = 0; kc < nch; kc++) {
            uint32_t mb = (kc & 1) ? smb + OF_MBAR + 8 : smb + OF_MBAR;
            uint32_t ab = (kc & 1) ? smb + OF_AB1 : smb + OF_AB0;
            unsigned& ccnt = (kc & 1) ? cA1 : cA0;
            mbar_wait(mb, ccnt & 1);
            ccnt++;
            bool dL0 = doL0 && kc < 8;
            uint32_t kb = (uint32_t)(kc * 128);
#pragma unroll
            for (int j = 0; j < 4; j++) {
                uint32_t a[2][4];
                LDSM4(a[0][0], a[0][1], a[0][2], a[0][3], ab + albase + j * 4096);
                LDSM4(a[1][0], a[1][1], a[1][2], a[1][3], ab + albase + j * 4096 + 256);
                if (dL0) {
                    uint32_t b[4];
                    LDSM4(b[0], b[1], b[2], b[3], bo0 + kb + j * 32);
                    mma16(aL0[0][0], a[0], b);     mma16(aL0[0][1], a[0], b + 2);
                    mma16(aL0[1][0], a[1], b);     mma16(aL0[1][1], a[1], b + 2);
                }
                if (doL1) {
                    uint32_t b[4];
                    LDSM4(b[0], b[1], b[2], b[3], bo1 + kb + j * 32);
                    mma16(aL1[0][0], a[0], b);     mma16(aL1[0][1], a[0], b + 2);
                    mma16(aL1[1][0], a[1], b);     mma16(aL1[1][1], a[1], b + 2);
                }
            }
            __syncthreads();
            if (tid == 0 && kc + 2 < nch) {
                int nk = kc + 2;
                const __half* sp = (nk < 8) ? p0 + (size_t)nk * 8192
                                            : p1 + (size_t)(nk - 8) * 8192;
                issue_bulk(ab, sp, 16384, mb);
            }
        }

        // ---- fused cells ----
        int nl = wn * 4 + ec;
        if (doL0) {
            mbar_wait(smb + OF_MBAR + 16, cXP & 1);
            cXP++;
            const __half* xpb = (const __half*)(smc + OF_XP);
#pragma unroll
            for (int mi = 0; mi < 2; mi++)
#pragma unroll
                for (int rh = 0; rh < 2; rh++) {
                    int row = wm * 32 + mi * 16 + rh * 8 + er;
                    uint2 xu = *(const uint2*)(xpb + row * 32 + nl * 4);
                    const __half* xh = (const __half*)&xu;
                    float g0 = aL0[mi][0][rh * 2]     + __half2float(xh[0]);
                    float g1 = aL0[mi][0][rh * 2 + 1] + __half2float(xh[1]);
                    float g2 = aL0[mi][1][rh * 2]     + __half2float(xh[2]);
                    float g3 = aL0[mi][1][rh * 2 + 1] + __half2float(xh[3]);
                    float ig = sigf(g0), fg = sigf(g1);
                    float gg = tanhf(g2), og = sigf(g3);
                    int ix = mi * 2 + rh;
                    float cv = fg * cst0[ix] + ig * gg;
                    cst0[ix] = cv;
                    ht0[row * 8 + nl] = __float2half(og * tanhf(cv));
                }
        }
        if (doL1) {
            const float* bp = bq1 + nl * 4;
#pragma unroll
            for (int mi = 0; mi < 2; mi++)
#pragma unroll
                for (int rh = 0; rh < 2; rh++) {
                    int row = wm * 32 + mi * 16 + rh * 8 + er;
                    float g0 = aL1[mi][0][rh * 2]     + bp[0];
                    float g1 = aL1[mi][0][rh * 2 + 1] + bp[1];
                    float g2 = aL1[mi][1][rh * 2]     + bp[2];
                    float g3 = aL1[mi][1][rh * 2 + 1] + bp[3];
                    float ig = sigf(g0), fg = sigf(g1);
                    float gg = tanhf(g2), og = sigf(g3);
                    int ix = mi * 2 + rh;
                    float cv = fg * cst1[ix] + ig * gg;
                    cst1[ix] = cv;
                    ht1[row * 8 + nl] = __float2half(og * tanhf(cv));
                    if (s == LL)
                        g_c1f[(size_t)(mh * 128 + row) * HH + nb * 8 + nl] = cv;
                }
        }
        __syncthreads();
        if (doL0 && tid < 128) {
            uint4 v = *(uint4*)(ht0 + tid * 8);
            *(uint4*)(g_h0[(s + 1) & 1] + (size_t)(mh * 8 + (nb >> 3)) * 8192 +
                      (size_t)((nb & 7) * 128 + tid) * 8) = v;
        }
        if (doL1 && tid >= 128) {
            int row = tid - 128;
            uint4 v = *(uint4*)(ht1 + row * 8);
            *(uint4*)(g_h1[s & 1] + (size_t)(mh * 8 + (nb >> 3)) * 8192 +
                      (size_t)((nb & 7) * 128 + row) * 8) = v;
            *(uint4*)(g_enc + (size_t)(s - 1) * BB * HH +
                      (size_t)(mh * 128 + row) * HH + nb * 8) = v;
        }
        gridbar(&g_bar_enc, round, NBE);
    }
}

// ---------------- DECODER ----------------
#define DOF_AB0  66048
#define DOF_AB1  82432
#define DOF_PA   98816
#define DOF_PMS  131584
#define DOF_BQ   131712
#define DOF_WD0  131840
#define DOF_MBAR 131968
#define DEC_SMEM 132096

template<int NQ, int KPAD>
__device__ __forceinline__ void mma_chunk(uint32_t abuf, uint32_t wsm, int kglob,
                                          float (&acc)[2][NQ*2][4],
                                          uint32_t albase, int bcol, int bkh) {
#pragma unroll
    for (int j = 0; j < 4; j++) {
        uint32_t a[2][4];
#pragma unroll
        for (int mi = 0; mi < 2; mi++)
            LDSM4(a[mi][0], a[mi][1], a[mi][2], a[mi][3],
                  abuf + albase + j * 4096 + mi * 256);
#pragma unroll
        for (int q = 0; q < NQ; q++) {
            uint32_t b[4];
            LDSM4(b[0], b[1], b[2], b[3],
                  wsm + (uint32_t)((bcol + q * 32) * KPAD + kglob + j * 16 + bkh) * 2);
#pragma unroll
            for (int mi = 0; mi < 2; mi++) {
                mma16(acc[mi][q * 2 + 0], a[mi], b);
                mma16(acc[mi][q * 2 + 1], a[mi], b + 2);
            }
        }
    }
}

template<int NCH, int NQ, int KPAD>
__device__ __forceinline__ void gemm_run(const __half* p0, const __half* p1,
                                         uint32_t wsm, uint32_t ab0, uint32_t ab1,
                                         uint32_t mb0, uint32_t mb1,
                                         float (&acc)[2][NQ*2][4],
                                         unsigned& c0, unsigned& c1,
                                         uint32_t albase, int bcol, int bkh, int tid) {
    if (tid == 0) {
        issue_bulk(ab0, p0, 16384, mb0);
        issue_bulk(ab1, p0 + 8192, 16384, mb1);
    }
    for (int kc = 0; kc < NCH; kc++) {
        uint32_t mb = (kc & 1) ? mb1 : mb0;
        uint32_t ab = (kc & 1) ? ab1 : ab0;
        unsigned& cc = (kc & 1) ? c1 : c0;
        mbar_wait(mb, cc & 1);
        cc++;
        mma_chunk<NQ, KPAD>(ab, wsm, kc * 64, acc, albase, bcol, bkh);
        __syncthreads();
        if (tid == 0 && kc + 2 < NCH) {
            int nk = kc + 2;
            const __half* s = (nk < 8) ? p0 + (size_t)nk * 8192
                                       : p1 + (size_t)(nk - 8) * 8192;
            issue_bulk(ab, s, 16384, mb);
        }
    }
}

__device__ __forceinline__ float dot8r(uint4 v, const float* s) {
    const __half2* h2 = (const __half2*)&v;
    float r = 0.f;
#pragma unroll
    for (int i = 0; i < 4; i++) {
        float2 f = __half22float2(h2[i]);
        r += f.x * s[2 * i] + f.y * s[2 * i + 1];
    }
    return r;
}
__device__ __forceinline__ void online_upd(float& M, float& S, float* C,
                                           float s1, uint4 v0, uint4 v1) {
    float mn = fmaxf(M, s1);
    float r = __expf(M - mn);
    float e = __expf(s1 - mn);
    S = S * r + e;
    const __half2* ha = (const __half2*)&v0;
    const __half2* hb = (const __half2*)&v1;
#pragma unroll
    for (int i = 0; i < 4; i++) {
        float2 f = __half22float2(ha[i]);
        C[2 * i]     = C[2 * i] * r + e * f.x;
        C[2 * i + 1] = C[2 * i + 1] * r + e * f.y;
        float2 f2 = __half22float2(hb[i]);
        C[8 + 2 * i]     = C[8 + 2 * i] * r + e * f2.x;
        C[8 + 2 * i + 1] = C[8 + 2 * i + 1] * r + e * f2.y;
    }
    M = mn;
}

// both batches (b0, b0+128) in one interleaved pass
__device__ void attn_two(int ds, int b0, bool full, const float* __restrict__ Wfc,
                         const float* __restrict__ bfc, float* __restrict__ out,
                         float* pa, float* pms) {
    int tid = threadIdx.x, lane = tid & 31, w = tid >> 5;
    int b1 = b0 + 128;
    const __half* h1b = g_h1[ds & 1];
    float hr0[16], hr1[16];
    {
        int mhB = b0 >> 7, rowB = b0 & 127;
        uint4 v0 = *(const uint4*)(h1b + (size_t)(mhB * 8 + (lane >> 3)) * 8192 +
                                   (size_t)((lane & 7) * 128 + rowB) * 8);
        uint4 v1 = *(const uint4*)(h1b + (size_t)(mhB * 8 + 4 + (lane >> 3)) * 8192 +
                                   (size_t)((lane & 7) * 128 + rowB) * 8);
        const __half* ha = (const __half*)&v0;
        const __half* hb = (const __half*)&v1;
#pragma unroll
        for (int i = 0; i < 8; i++) {
            hr0[i] = __half2float(ha[i]);
            hr0[8 + i] = __half2float(hb[i]);
        }
    }
    {
        int mhB = b1 >> 7, rowB = b1 & 127;
        uint4 v0 = *(const uint4*)(h1b + (size_t)(mhB * 8 + (lane >> 3)) * 8192 +
                                   (size_t)((lane & 7) * 128 + rowB) * 8);
        uint4 v1 = *(const uint4*)(h1b + (size_t)(mhB * 8 + 4 + (lane >> 3)) * 8192 +
                                   (size_t)((lane & 7) * 128 + rowB) * 8);
        const __half* ha = (const __half*)&v0;
        const __half* hb = (const __half*)&v1;
#pragma unroll
        for (int i = 0; i < 8; i++) {
            hr1[i] = __half2float(ha[i]);
            hr1[8 + i] = __half2float(hb[i]);
        }
    }
    if (w == 0) {
        float yv = 0.f;
#pragma unroll
        for (int i = 0; i < 8; i++)
            yv += hr0[i] * Wfc[lane * 8 + i] + hr0[8 + i] * Wfc[256 + lane * 8 + i];
#pragma unroll
        for (int off = 16; off; off >>= 1) yv += __shfl_xor_sync(0xffffffffu, yv, off);
        if (lane == 0) {
            float y = yv + bfc[0];
            if (ds > 0) out[b0 * PL + ds - 1] = y;
            g_yprev[b0] = (ds == 0) ? 0.f : y;
        }
    } else if (w == 1) {
        float yv = 0.f;
#pragma unroll
        for (int i = 0; i < 8; i++)
            yv += hr1[i] * Wfc[lane * 8 + i] + hr1[8 + i] * Wfc[256 + lane * 8 + i];
#pragma unroll
        for (int off = 16; off; off >>= 1) yv += __shfl_xor_sync(0xffffffffu, yv, off);
        if (lane == 0) {
            float y = yv + bfc[0];
            if (ds > 0) out[b1 * PL + ds - 1] = y;
            g_yprev[b1] = (ds == 0) ? 0.f : y;
        }
    }
    if (!full) return;

    float M0 = -1e30f, S0 = 0.f, C0[16];
    float M1 = -1e30f, S1 = 0.f, C1[16];
#pragma unroll
    for (int i = 0; i < 16; i++) { C0[i] = 0.f; C1[i] = 0.f; }
    for (int l = w; l < LL; l += 8) {
        const uint4* e0 = (const uint4*)(g_enc + ((size_t)l * BB + b0) * HH);
        const uint4* e1 = (const uint4*)(g_enc + ((size_t)l * BB + b1) * HH);
        uint4 v00 = e0[lane], v01 = e0[lane + 32];
        uint4 v10 = e1[lane], v11 = e1[lane + 32];
        float s0 = dot8r(v00, hr0) + dot8r(v01, hr0 + 8);
        float s1 = dot8r(v10, hr1) + dot8r(v11, hr1 + 8);
#pragma unroll
        for (int off = 16; off; off >>= 1) {
            s0 += __shfl_xor_sync(0xffffffffu, s0, off);
            s1 += __shfl_xor_sync(0xffffffffu, s1, off);
        }
        online_upd(M0, S0, C0, s0, v00, v01);
        online_upd(M1, S1, C1, s1, v10, v11);
    }
    if (lane == 0) {
        pms[w * 2] = M0;      pms[w * 2 + 1] = S0;
        pms[16 + w * 2] = M1; pms[16 + w * 2 + 1] = S1;
    }
#pragma unroll
    for (int i = 0; i < 8; i++) {
        pa[w * 512 + lane * 8 + i]       = C0[i];
        pa[w * 512 + 256 + lane * 8 + i] = C0[8 + i];
        pa[4096 + w * 512 + lane * 8 + i]       = C1[i];
        pa[4096 + w * 512 + 256 + lane * 8 + i] = C1[8 + i];
    }
    __syncthreads();
#pragma unroll
    for (int bb = 0; bb < 2; bb++) {
        int b = bb ? b1 : b0;
        int mhB = b >> 7, rowB = b & 127;
        const float* pm = pms + bb * 16;
        const float* pp = pa + bb * 4096;
        float Mg = -1e30f;
#pragma unroll
        for (int ww = 0; ww < 8; ww++) Mg = fmaxf(Mg, pm[ww * 2]);
        float Sg = 0.f;
        float scl[8];
#pragma unroll
        for (int ww = 0; ww < 8; ww++) {
            scl[ww] = __expf(pm[ww * 2] - Mg);
            Sg += pm[ww * 2 + 1] * scl[ww];
        }
        float inv = 1.f / Sg;
        for (int h = tid; h < HH; h += 256) {
            float a = 0.f;
#pragma unroll
            for (int ww = 0; ww < 8; ww++) a += pp[ww * 512 + h] * scl[ww];
            g_ctxc[(size_t)(mhB * 8 + (h >> 6)) * 8192 +
                   (size_t)(((h & 63) >> 3) * 128 + rowB) * 8 + (h & 7)] =
                __float2half(a * inv);
        }
    }
    __syncthreads();
}

__global__ void __launch_bounds__(256, 1) dec_persistent(
    const float* __restrict__ Wdi, const float* __restrict__ Wdh,
    const float* __restrict__ bdi, const float* __restrict__ bdh,
    const float* __restrict__ Wfc, const float* __restrict__ bfc,
    float* __restrict__ out) {
    extern __shared__ __align__(16) char smc[];
    __half* Wsm = (__half*)smc;
    float* pa  = (float*)(smc + DOF_PA);
    float* pms = (float*)(smc + DOF_PMS);
    float* bqd = (float*)(smc + DOF_BQ);
    float* wd0 = (float*)(smc + DOF_WD0);
    uint32_t smb = smem_u32(smc);

    int bx = blockIdx.x, tid = threadIdx.x;
    int lane = tid & 31, wid = tid >> 5;
    int wm = wid >> 1, wn = wid & 1;
    int i4 = lane >> 3, r8 = lane & 7;
    int er = lane >> 2, ec = lane & 3;
    int mh = bx & 1;
    int nb8 = (bx >> 1) * 8;

    for (int idx = tid; idx < 32 * 256; idx += 256) {
        int cc = idx >> 8, k4 = (idx & 255) * 4;
        int gate = (cc & 1) | (((cc >> 3) & 1) << 1);
        int n = nb8 + ((cc >> 4) & 1) * 4 + ((cc >> 1) & 3);
        int row = gate * HH + n;
        float w4[4];
        if (k4 < HH) {
            const float* sp = Wdi + (size_t)row * (HH + 1) + 1 + k4;
            w4[0] = sp[0]; w4[1] = sp[1]; w4[2] = sp[2]; w4[3] = sp[3];
        } else {
            float4 wv = *(const float4*)(Wdh + (size_t)row * HH + (k4 - HH));
            w4[0] = wv.x; w4[1] = wv.y; w4[2] = wv.z; w4[3] = wv.w;
        }
        __half* d = Wsm + (size_t)cc * 1032 + k4;
        d[0] = __float2half(w4[0]); d[1] = __float2half(w4[1]);
        d[2] = __float2half(w4[2]); d[3] = __float2half(w4[3]);
    }
    if (tid < 32) {
        int nl = tid >> 2, g = tid & 3;
        int row = g * HH + nb8 + nl;
        bqd[nl * 4 + g] = bdi[row] + bdh[row];
        wd0[nl * 4 + g] = Wdi[(size_t)row * (HH + 1)];
    }
    if (tid == 0) {
        mbar_init(smb + DOF_MBAR, 1);
        mbar_init(smb + DOF_MBAR + 8, 1);
    }
    __syncthreads();

    uint32_t albase = ((uint32_t)((i4 >> 1) & 1)) * 2048 +
                      (uint32_t)(wm * 32 + (i4 & 1) * 8 + r8) * 16;
    int bcol = wn * 16 + ((i4 >> 1) & 1) * 8 + r8;
    int bkh = (i4 & 1) * 8;

    float cst[4];
#pragma unroll
    for (int mi = 0; mi < 2; mi++)
#pragma unroll
        for (int rh = 0; rh < 2; rh++) {
            int b = mh * 128 + wm * 32 + mi * 16 + rh * 8 + er;
            cst[mi * 2 + rh] = g_c1f[(size_t)b * HH + nb8 + wn * 4 + ec];
        }

    unsigned cA0 = 0, cA1 = 0;
    unsigned round = 0;
    for (int ds = 0; ds <= PL; ds++) {
        attn_two(ds, bx, ds < PL, Wfc, bfc, out, pa, pms);
        if (ds == PL) break;
        gridbar(&g_bar_dec, round, NBD);

        float acc[2][2][4];
#pragma unroll
        for (int a = 0; a < 2; a++)
#pragma unroll
            for (int b = 0; b < 2; b++)
#pragma unroll
                for (int qd = 0; qd < 4; qd++) acc[a][b][qd] = 0.f;
        const __half* p0 = g_ctxc + (size_t)mh * 8 * 8192;
        const __half* p1 = g_h1[ds & 1] + (size_t)mh * 8 * 8192;
        gemm_run<16, 1, 1032>(p0, p1, smb, smb + DOF_AB0, smb + DOF_AB1,
                              smb + DOF_MBAR, smb + DOF_MBAR + 8,
                              acc, cA0, cA1, albase, bcol, bkh, tid);
        {
            int nl = wn * 4 + ec;
            int n = nb8 + nl;
            int kc = n >> 6;
            int seg = (n & 63) >> 3;
            __half* hb = g_h1[(ds + 1) & 1];
#pragma unroll
            for (int mi = 0; mi < 2; mi++)
#pragma unroll
                for (int rh = 0; rh < 2; rh++) {
                    int row = wm * 32 + mi * 16 + rh * 8 + er;
                    int b = mh * 128 + row;
                    float y = g_yprev[b];
                    const float* bp = bqd + nl * 4;
                    const float* wp = wd0 + nl * 4;
                    float g0 = acc[mi][0][rh * 2]     + bp[0] + wp[0] * y;
                    float g1 = acc[mi][0][rh * 2 + 1] + bp[1] + wp[1] * y;
                    float g2 = acc[mi][1][rh * 2]     + bp[2] + wp[2] * y;
                    float g3 = acc[mi][1][rh * 2 + 1] + bp[3] + wp[3] * y;
                    float ig = sigf(g0), fg = sigf(g1);
                    float gg = tanhf(g2), og = sigf(g3);
                    float cv = fg * cst[mi * 2 + rh] + ig * gg;
                    cst[mi * 2 + rh] = cv;
                    hb[(size_t)(mh * 8 + kc) * 8192 + (size_t)(seg * 128 + row) * 8 +
                       (n & 7)] = __float2half(og * tanhf(cv));
                }
        }
        gridbar(&g_bar_dec, round, NBD);
    }
}

extern "C" void kernel_launch(void* const* d_in, const int* in_sizes, int n_in,
                              void* d_out, int out_size) {
    const float* x    = (const float*)d_in[0];
    const float* Wih0 = (const float*)d_in[1];
    const float* Whh0 = (const float*)d_in[2];
    const float* bi0  = (const float*)d_in[3];
    const float* bh0  = (const float*)d_in[4];
    const float* Wih1 = (const float*)d_in[5];
    const float* Whh1 = (const float*)d_in[6];
    const float* bi1  = (const float*)d_in[7];
    const float* bh1  = (const float*)d_in[8];
    const float* Wdi  = (const float*)d_in[9];
    const float* Wdh  = (const float*)d_in[10];
    const float* bdi  = (const float*)d_in[11];
    const float* bdh  = (const float*)d_in[12];
    const float* Wfc  = (const float*)d_in[13];
    const float* bfc  = (const float*)d_in[14];
    float* out = (float*)d_out;

    cudaFuncSetAttribute(enc_persistent, cudaFuncAttributeMaxDynamicSharedMemorySize, ENC_SMEM);
    cudaFuncSetAttribute(dec_persistent, cudaFuncAttributeMaxDynamicSharedMemorySize, DEC_SMEM);

    prep_kernel<<<(BB * HH + 255) / 256, 256>>>();
    xp_kernel<<<dim3(LL, 128), 256>>>(x, Wih0, bi0, bh0);
    enc_persistent<<<NBE, 256, ENC_SMEM>>>(Whh0, Wih1, Whh1, bi1, bh1);
    dec_persistent<<<NBD, 256, DEC_SMEM>>>(Wdi, Wdh, bdi, bdh, Wfc, bfc, out);
}

// round 11
// speedup vs baseline: 1.6196x; 1.0141x over previous
#include <cuda_runtime.h>
#include <cuda_fp16.h>
#include <stdint.h>

#define BB 256
#define LL 336
#define NIN 8
#define HH 512
#define PL 96
#define NBE 128
#define NBD 128

// chunked h layout: [mh*8+kc] chunks of 8192 halves; within chunk:
// elem(row,klocal) at ((klocal>>3)*128 + row)*8 + (klocal&7)
__device__ __align__(128) __half g_h0[2][BB*HH];
__device__ __align__(128) __half g_h1[2][BB*HH];
__device__ __align__(128) __half g_ctxc[BB*HH];
__device__ float  g_c1f[BB*HH];
__device__ float  g_yprev[BB];
__device__ __align__(128) __half g_enc[(size_t)LL*BB*HH];     // [l][b][n]
__device__ __align__(128) __half g_xp[(size_t)LL*BB*2048];    // [s][cta128][row128][nl8][4]
__device__ unsigned g_bar_enc, g_bar_dec;

__device__ __forceinline__ float sigf(float x) { return 1.f / (1.f + __expf(-x)); }

__device__ __forceinline__ void gridbar(unsigned* bar, unsigned& round, unsigned nblk) {
    round++;
    __syncthreads();
    __threadfence();
    if (threadIdx.x == 0) {
        unsigned target = round * nblk;
        atomicAdd(bar, 1u);
        while (*(volatile unsigned*)bar < target) { }
        __threadfence();
    }
    __syncthreads();
}

__device__ __forceinline__ uint32_t smem_u32(const void* p) {
    uint32_t a;
    asm("{ .reg .u64 t; cvta.to.shared.u64 t, %1; cvt.u32.u64 %0, t; }" : "=r"(a) : "l"(p));
    return a;
}
__device__ __forceinline__ void mma16(float c[4], const uint32_t a[4], const uint32_t b[2]) {
    asm volatile(
        "mma.sync.aligned.m16n8k16.row.col.f32.f16.f16.f32 "
        "{%0,%1,%2,%3},{%4,%5,%6,%7},{%8,%9},{%0,%1,%2,%3};"
        : "+f"(c[0]), "+f"(c[1]), "+f"(c[2]), "+f"(c[3])
        : "r"(a[0]), "r"(a[1]), "r"(a[2]), "r"(a[3]), "r"(b[0]), "r"(b[1]));
}
#define LDSM4(r0, r1, r2, r3, addr) \
    asm volatile("ldmatrix.sync.aligned.m8n8.x4.shared.b16 {%0,%1,%2,%3},[%4];" \
                 : "=r"(r0), "=r"(r1), "=r"(r2), "=r"(r3) : "r"(addr))

__device__ __forceinline__ void mbar_init(uint32_t mbar, uint32_t cnt) {
    asm volatile("mbarrier.init.shared.b64 [%0], %1;" :: "r"(mbar), "r"(cnt) : "memory");
}
__device__ __forceinline__ void mbar_wait(uint32_t mbar, uint32_t parity) {
    uint32_t done = 0;
    while (!done) {
        asm volatile(
            "{\n\t.reg .pred p;\n\t"
            "mbarrier.try_wait.parity.acquire.cta.shared::cta.b64 p, [%1], %2, 0x989680;\n\t"
            "selp.b32 %0, 1, 0, p;\n\t}"
            : "=r"(done) : "r"(mbar), "r"(parity) : "memory");
    }
}
__device__ __forceinline__ void issue_bulk(uint32_t dst, const void* src, uint32_t bytes,
                                           uint32_t mbar) {
    asm volatile("mbarrier.arrive.expect_tx.shared.b64 _, [%0], %1;"
                 :: "r"(mbar), "r"(bytes) : "memory");
    asm volatile(
        "cp.async.bulk.shared::cluster.global.mbarrier::complete_tx::bytes [%0], [%1], %2, [%3];"
        :: "r"(dst), "l"(src), "r"(bytes), "r"(mbar) : "memory");
}

// ---------------- prep + xp ----------------
__global__ void prep_kernel() {
    int i = blockIdx.x * blockDim.x + threadIdx.x;
    if (i < BB * HH) {
        g_h0[0][i] = __float2half(0.f);
        g_h1[0][i] = __float2half(0.f);
    }
    if (i == 0) { g_bar_enc = 0u; g_bar_dec = 0u; }
}

__global__ void xp_kernel(const float* __restrict__ x, const float* __restrict__ Wih0,
                          const float* __restrict__ bi0, const float* __restrict__ bh0) {
    int s = blockIdx.x, c = blockIdx.y, tid = threadIdx.x;
    int mh = c & 1, nb = c >> 1;
    __shared__ float xs[128 * 8];
    __shared__ float Wq[8 * 4 * 8];
    __shared__ float bq[32];
    for (int idx = tid; idx < 1024; idx += 256) {
        int bl = idx >> 3, k = idx & 7;
        xs[idx] = x[((size_t)(mh * 128 + bl) * LL + s) * NIN + k];
    }
    if (tid < 256) {
        int nl = tid >> 5, g = (tid >> 3) & 3, k = tid & 7;
        Wq[tid] = Wih0[(g * HH + nb * 8 + nl) * NIN + k];
    }
    if (tid < 32) {
        int nl = tid >> 2, g = tid & 3;
        bq[tid] = bi0[g * HH + nb * 8 + nl] + bh0[g * HH + nb * 8 + nl];
    }
    __syncthreads();
    int row = tid & 127, part = tid >> 7;
    const float* xr = xs + row * 8;
    __half q16[16];
#pragma unroll
    for (int u = 0; u < 4; u++) {
        int nl = part * 4 + u;
#pragma unroll
        for (int g = 0; g < 4; g++) {
            const float* wr = Wq + (nl * 4 + g) * 8;
            float a = bq[nl * 4 + g];
#pragma unroll
            for (int k = 0; k < 8; k++) a += wr[k] * xr[k];
            q16[u * 4 + g] = __float2half(a);
        }
    }
    __half* dst = g_xp + ((size_t)s * 128 + c) * 4096 + row * 32 + part * 16;
    *(uint4*)(dst)     = *(uint4*)(q16);
    *(uint4*)(dst + 8) = *(uint4*)(q16 + 8);
}

// ---------------- ENCODER: unified 128 CTAs, 4-buffer ring, sync recycling ----------------
#define OF_WL1  33280
#define OF_AB   99328
#define OF_XP   164864
#define OF_HT0  173056
#define OF_HT1  175104
#define OF_B1   177152
#define OF_MBAR 177280
#define ENC_SMEM 177408

__global__ void __launch_bounds__(256, 1) enc_persistent(
    const float* __restrict__ Whh0, const float* __restrict__ Wih1,
    const float* __restrict__ Whh1,
    const float* __restrict__ bi1, const float* __restrict__ bh1) {
    extern __shared__ __align__(16) char smc[];
    __half* WL0 = (__half*)smc;
    __half* WL1 = (__half*)(smc + OF_WL1);
    __half* ht0 = (__half*)(smc + OF_HT0);
    __half* ht1 = (__half*)(smc + OF_HT1);
    float*  bq1 = (float*)(smc + OF_B1);
    uint32_t smb = smem_u32(smc);

    int bx = blockIdx.x, tid = threadIdx.x;
    int lane = tid & 31, wid = tid >> 5;
    int wm = wid >> 1, wn = wid & 1;
    int i4 = lane >> 3, r8 = lane & 7;
    int er = lane >> 2, ec = lane & 3;
    int mh = bx & 1, nb = bx >> 1;

    // ---- weights to smem (32 cols, gate-permuted) ----
    for (int idx = tid; idx < 32 * 128; idx += 256) {
        int cc = idx >> 7, k4 = (idx & 127) * 4;
        int gate = (cc & 1) | (((cc >> 3) & 1) << 1);
        int n = nb * 8 + ((cc >> 4) & 1) * 4 + ((cc >> 1) & 3);
        float4 w = *(const float4*)(Whh0 + (size_t)(gate * HH + n) * HH + k4);
        __half* d = WL0 + (size_t)cc * 520 + k4;
        d[0] = __float2half(w.x); d[1] = __float2half(w.y);
        d[2] = __float2half(w.z); d[3] = __float2half(w.w);
    }
    for (int idx = tid; idx < 32 * 256; idx += 256) {
        int cc = idx >> 8, k4 = (idx & 255) * 4;
        int gate = (cc & 1) | (((cc >> 3) & 1) << 1);
        int n = nb * 8 + ((cc >> 4) & 1) * 4 + ((cc >> 1) & 3);
        int row = gate * HH + n;
        const float* srcW = (k4 < HH) ? Wih1 + (size_t)row * HH + k4
                                      : Whh1 + (size_t)row * HH + (k4 - HH);
        float4 w = *(const float4*)srcW;
        __half* d = WL1 + (size_t)cc * 1032 + k4;
        d[0] = __float2half(w.x); d[1] = __float2half(w.y);
        d[2] = __float2half(w.z); d[3] = __float2half(w.w);
    }
    if (tid < 32) {
        int nl = tid >> 2, g = tid & 3;
        int n = nb * 8 + nl;
        bq1[tid] = bi1[g * HH + n] + bh1[g * HH + n];
    }
    if (tid == 0) {
#pragma unroll
        for (int p = 0; p < 4; p++) mbar_init(smb + OF_MBAR + p * 8, 1);
        mbar_init(smb + OF_MBAR + 32, 1);   // xp
    }
    __syncthreads();

    uint32_t albase = ((uint32_t)((i4 >> 1) & 1)) * 2048 +
                      (uint32_t)(wm * 32 + (i4 & 1) * 8 + r8) * 16;
    int bcol = wn * 16 + ((i4 >> 1) & 1) * 8 + r8;
    int bkh = (i4 & 1) * 8;
    uint32_t bo0 = smb + (uint32_t)(bcol * 520 + bkh) * 2;
    uint32_t bo1 = smb + OF_WL1 + (uint32_t)(bcol * 1032 + bkh) * 2;

    float cst0[4], cst1[4];
#pragma unroll
    for (int i = 0; i < 4; i++) { cst0[i] = 0.f; cst1[i] = 0.f; }

    unsigned cF[4] = {0, 0, 0, 0}, cXP = 0;
    unsigned round = 0;
    for (int s = 0; s <= LL; s++) {
        bool doL0 = (s < LL), doL1 = (s >= 1);
        int nch = doL1 ? 16 : 8;
        const __half* p0 = g_h0[s & 1] + (size_t)mh * 8 * 8192;
        const __half* p1 = g_h1[(s + 1) & 1] + (size_t)mh * 8 * 8192;

        if (tid == 0) {
            if (doL0)
                issue_bulk(smb + OF_XP, g_xp + ((size_t)s * 128 + bx) * 4096, 8192,
                           smb + OF_MBAR + 32);
#pragma unroll
            for (int p = 0; p < 4; p++)
                issue_bulk(smb + OF_AB + p * 16384, p0 + (size_t)p * 8192, 16384,
                           smb + OF_MBAR + p * 8);
        }

        float aL0[2][2][4], aL1[2][2][4];
#pragma unroll
        for (int a = 0; a < 2; a++)
#pragma unroll
            for (int b = 0; b < 2; b++)
#pragma unroll
                for (int q = 0; q < 4; q++) { aL0[a][b][q] = 0.f; aL1[a][b][q] = 0.f; }

        for (int kc = 0; kc < nch; kc++) {
            int p = kc & 3;
            mbar_wait(smb + OF_MBAR + p * 8, cF[p] & 1);
            cF[p]++;
            bool dL0 = doL0 && kc < 8;
            uint32_t ab = smb + OF_AB + p * 16384;
            uint32_t kb = (uint32_t)(kc * 128);
#pragma unroll
            for (int j = 0; j < 4; j++) {
                uint32_t a[2][4];
                LDSM4(a[0][0], a[0][1], a[0][2], a[0][3], ab + albase + j * 4096);
                LDSM4(a[1][0], a[1][1], a[1][2], a[1][3], ab + albase + j * 4096 + 256);
                if (dL0) {
                    uint32_t b[4];
                    LDSM4(b[0], b[1], b[2], b[3], bo0 + kb + j * 32);
                    mma16(aL0[0][0], a[0], b);     mma16(aL0[0][1], a[0], b + 2);
                    mma16(aL0[1][0], a[1], b);     mma16(aL0[1][1], a[1], b + 2);
                }
                if (doL1) {
                    uint32_t b[4];
                    LDSM4(b[0], b[1], b[2], b[3], bo1 + kb + j * 32);
                    mma16(aL1[0][0], a[0], b);     mma16(aL1[0][1], a[0], b + 2);
                    mma16(aL1[1][0], a[1], b);     mma16(aL1[1][1], a[1], b + 2);
                }
            }
            __syncthreads();   // all warps done reading buffer p
            if (tid == 0 && kc + 4 < nch) {
                int nk = kc + 4;
                const __half* sp = (nk < 8) ? p0 + (size_t)nk * 8192
                                            : p1 + (size_t)(nk - 8) * 8192;
                issue_bulk(ab, sp, 16384, smb + OF_MBAR + p * 8);
            }
        }

        // ---- fused cells ----
        int nl = wn * 4 + ec;
        if (doL0) {
            mbar_wait(smb + OF_MBAR + 32, cXP & 1);
            cXP++;
            const __half* xpb = (const __half*)(smc + OF_XP);
#pragma unroll
            for (int mi = 0; mi < 2; mi++)
#pragma unroll
                for (int rh = 0; rh < 2; rh++) {
                    int row = wm * 32 + mi * 16 + rh * 8 + er;
                    uint2 xu = *(const uint2*)(xpb + row * 32 + nl * 4);
                    const __half* xh = (const __half*)&xu;
                    float g0 = aL0[mi][0][rh * 2]     + __half2float(xh[0]);
                    float g1 = aL0[mi][0][rh * 2 + 1] + __half2float(xh[1]);
                    float g2 = aL0[mi][1][rh * 2]     + __half2float(xh[2]);
                    float g3 = aL0[mi][1][rh * 2 + 1] + __half2float(xh[3]);
                    float ig = sigf(g0), fg = sigf(g1);
                    float gg = tanhf(g2), og = sigf(g3);
                    int ix = mi * 2 + rh;
                    float cv = fg * cst0[ix] + ig * gg;
                    cst0[ix] = cv;
                    ht0[row * 8 + nl] = __float2half(og * tanhf(cv));
                }
        }
        if (doL1) {
            const float* bp = bq1 + nl * 4;
#pragma unroll
            for (int mi = 0; mi < 2; mi++)
#pragma unroll
                for (int rh = 0; rh < 2; rh++) {
                    int row = wm * 32 + mi * 16 + rh * 8 + er;
                    float g0 = aL1[mi][0][rh * 2]     + bp[0];
                    float g1 = aL1[mi][0][rh * 2 + 1] + bp[1];
                    float g2 = aL1[mi][1][rh * 2]     + bp[2];
                    float g3 = aL1[mi][1][rh * 2 + 1] + bp[3];
                    float ig = sigf(g0), fg = sigf(g1);
                    float gg = tanhf(g2), og = sigf(g3);
                    int ix = mi * 2 + rh;
                    float cv = fg * cst1[ix] + ig * gg;
                    cst1[ix] = cv;
                    ht1[row * 8 + nl] = __float2half(og * tanhf(cv));
                    if (s == LL)
                        g_c1f[(size_t)(mh * 128 + row) * HH + nb * 8 + nl] = cv;
                }
        }
        __syncthreads();
        if (doL0 && tid < 128) {
            uint4 v = *(uint4*)(ht0 + tid * 8);
            *(uint4*)(g_h0[(s + 1) & 1] + (size_t)(mh * 8 + (nb >> 3)) * 8192 +
                      (size_t)((nb & 7) * 128 + tid) * 8) = v;
        }
        if (doL1 && tid >= 128) {
            int row = tid - 128;
            uint4 v = *(uint4*)(ht1 + row * 8);
            *(uint4*)(g_h1[s & 1] + (size_t)(mh * 8 + (nb >> 3)) * 8192 +
                      (size_t)((nb & 7) * 128 + row) * 8) = v;
            *(uint4*)(g_enc + (size_t)(s - 1) * BB * HH +
                      (size_t)(mh * 128 + row) * HH + nb * 8) = v;
        }
        gridbar(&g_bar_enc, round, NBE);
    }
}

// ---------------- DECODER ----------------
#define DOF_AB   66048
#define DOF_PA   131584
#define DOF_PMS  164352
#define DOF_BQ   164480
#define DOF_WD0  164608
#define DOF_MBAR 164736
#define DEC_SMEM 164864

template<int NQ, int KPAD>
__device__ __forceinline__ void mma_chunk(uint32_t abuf, uint32_t wsm, int kglob,
                                          float (&acc)[2][NQ*2][4],
                                          uint32_t albase, int bcol, int bkh) {
#pragma unroll
    for (int j = 0; j < 4; j++) {
        uint32_t a[2][4];
#pragma unroll
        for (int mi = 0; mi < 2; mi++)
            LDSM4(a[mi][0], a[mi][1], a[mi][2], a[mi][3],
                  abuf + albase + j * 4096 + mi * 256);
#pragma unroll
        for (int q = 0; q < NQ; q++) {
            uint32_t b[4];
            LDSM4(b[0], b[1], b[2], b[3],
                  wsm + (uint32_t)((bcol + q * 32) * KPAD + kglob + j * 16 + bkh) * 2);
#pragma unroll
            for (int mi = 0; mi < 2; mi++) {
                mma16(acc[mi][q * 2 + 0], a[mi], b);
                mma16(acc[mi][q * 2 + 1], a[mi], b + 2);
            }
        }
    }
}

// one 8-chunk half; buffers recycled via __syncthreads
__device__ __forceinline__ void dec_half(const __half* base, int kc0, uint32_t smb,
                                         float (&acc)[2][2][4], unsigned (&cF)[4],
                                         uint32_t albase, int bcol, int bkh, int tid) {
    for (int i = 0; i < 8; i++) {
        int p = i & 3;
        mbar_wait(smb + DOF_MBAR + p * 8, cF[p] & 1);
        cF[p]++;
        mma_chunk<1, 1032>(smb + DOF_AB + p * 16384, smb, (kc0 + i) * 64, acc,
                           albase, bcol, bkh);
        __syncthreads();
        if (tid == 0 && i + 4 < 8)
            issue_bulk(smb + DOF_AB + p * 16384, base + (size_t)(i + 4) * 8192, 16384,
                       smb + DOF_MBAR + p * 8);
    }
}

__device__ __forceinline__ float dot8r(uint4 v, const float* s) {
    const __half2* h2 = (const __half2*)&v;
    float r = 0.f;
#pragma unroll
    for (int i = 0; i < 4; i++) {
        float2 f = __half22float2(h2[i]);
        r += f.x * s[2 * i] + f.y * s[2 * i + 1];
    }
    return r;
}
__device__ __forceinline__ void online_upd(float& M, float& S, float* C,
                                           float s1, uint4 v0, uint4 v1) {
    float mn = fmaxf(M, s1);
    float r = __expf(M - mn);
    float e = __expf(s1 - mn);
    S = S * r + e;
    const __half2* ha = (const __half2*)&v0;
    const __half2* hb = (const __half2*)&v1;
#pragma unroll
    for (int i = 0; i < 4; i++) {
        float2 f = __half22float2(ha[i]);
        C[2 * i]     = C[2 * i] * r + e * f.x;
        C[2 * i + 1] = C[2 * i + 1] * r + e * f.y;
        float2 f2 = __half22float2(hb[i]);
        C[8 + 2 * i]     = C[8 + 2 * i] * r + e * f2.x;
        C[8 + 2 * i + 1] = C[8 + 2 * i + 1] * r + e * f2.y;
    }
    M = mn;
}

__device__ void attn_two(int ds, int b0, bool full, const float* __restrict__ Wfc,
                         const float* __restrict__ bfc, float* __restrict__ out,
                         float* pa, float* pms) {
    int tid = threadIdx.x, lane = tid & 31, w = tid >> 5;
    int b1 = b0 + 128;
    const __half* h1b = g_h1[ds & 1];
    float hr0[16], hr1[16];
    {
        int mhB = b0 >> 7, rowB = b0 & 127;
        uint4 v0 = *(const uint4*)(h1b + (size_t)(mhB * 8 + (lane >> 3)) * 8192 +
                                   (size_t)((lane & 7) * 128 + rowB) * 8);
        uint4 v1 = *(const uint4*)(h1b + (size_t)(mhB * 8 + 4 + (lane >> 3)) * 8192 +
                                   (size_t)((lane & 7) * 128 + rowB) * 8);
        const __half* ha = (const __half*)&v0;
        const __half* hb = (const __half*)&v1;
#pragma unroll
        for (int i = 0; i < 8; i++) {
            hr0[i] = __half2float(ha[i]);
            hr0[8 + i] = __half2float(hb[i]);
        }
    }
    {
        int mhB = b1 >> 7, rowB = b1 & 127;
        uint4 v0 = *(const uint4*)(h1b + (size_t)(mhB * 8 + (lane >> 3)) * 8192 +
                                   (size_t)((lane & 7) * 128 + rowB) * 8);
        uint4 v1 = *(const uint4*)(h1b + (size_t)(mhB * 8 + 4 + (lane >> 3)) * 8192 +
                                   (size_t)((lane & 7) * 128 + rowB) * 8);
        const __half* ha = (const __half*)&v0;
        const __half* hb = (const __half*)&v1;
#pragma unroll
        for (int i = 0; i < 8; i++) {
            hr1[i] = __half2float(ha[i]);
            hr1[8 + i] = __half2float(hb[i]);
        }
    }
    if (w == 0) {
        float yv = 0.f;
#pragma unroll
        for (int i = 0; i < 8; i++)
            yv += hr0[i] * Wfc[lane * 8 + i] + hr0[8 + i] * Wfc[256 + lane * 8 + i];
#pragma unroll
        for (int off = 16; off; off >>= 1) yv += __shfl_xor_sync(0xffffffffu, yv, off);
        if (lane == 0) {
            float y = yv + bfc[0];
            if (ds > 0) out[b0 * PL + ds - 1] = y;
            g_yprev[b0] = (ds == 0) ? 0.f : y;
        }
    } else if (w == 1) {
        float yv = 0.f;
#pragma unroll
        for (int i = 0; i < 8; i++)
            yv += hr1[i] * Wfc[lane * 8 + i] + hr1[8 + i] * Wfc[256 + lane * 8 + i];
#pragma unroll
        for (int off = 16; off; off >>= 1) yv += __shfl_xor_sync(0xffffffffu, yv, off);
        if (lane == 0) {
            float y = yv + bfc[0];
            if (ds > 0) out[b1 * PL + ds - 1] = y;
            g_yprev[b1] = (ds == 0) ? 0.f : y;
        }
    }
    if (!full) return;

    float M0 = -1e30f, S0 = 0.f, C0[16];
    float M1 = -1e30f, S1 = 0.f, C1[16];
#pragma unroll
    for (int i = 0; i < 16; i++) { C0[i] = 0.f; C1[i] = 0.f; }
    for (int l = w; l < LL; l += 8) {
        const uint4* e0 = (const uint4*)(g_enc + ((size_t)l * BB + b0) * HH);
        const uint4* e1 = (const uint4*)(g_enc + ((size_t)l * BB + b1) * HH);
        uint4 v00 = e0[lane], v01 = e0[lane + 32];
        uint4 v10 = e1[lane], v11 = e1[lane + 32];
        float s0 = dot8r(v00, hr0) + dot8r(v01, hr0 + 8);
        float s1 = dot8r(v10, hr1) + dot8r(v11, hr1 + 8);
#pragma unroll
        for (int off = 16; off; off >>= 1) {
            s0 += __shfl_xor_sync(0xffffffffu, s0, off);
            s1 += __shfl_xor_sync(0xffffffffu, s1, off);
        }
        online_upd(M0, S0, C0, s0, v00, v01);
        online_upd(M1, S1, C1, s1, v10, v11);
    }
    if (lane == 0) {
        pms[w * 2] = M0;      pms[w * 2 + 1] = S0;
        pms[16 + w * 2] = M1; pms[16 + w * 2 + 1] = S1;
    }
#pragma unroll
    for (int i = 0; i < 8; i++) {
        pa[w * 512 + lane * 8 + i]       = C0[i];
        pa[w * 512 + 256 + lane * 8 + i] = C0[8 + i];
        pa[4096 + w * 512 + lane * 8 + i]       = C1[i];
        pa[4096 + w * 512 + 256 + lane * 8 + i] = C1[8 + i];
    }
    __syncthreads();
#pragma unroll
    for (int bb = 0; bb < 2; bb++) {
        int b = bb ? b1 : b0;
        int mhB = b >> 7, rowB = b & 127;
        const float* pm = pms + bb * 16;
        const float* pp = pa + bb * 4096;
        float Mg = -1e30f;
#pragma unroll
        for (int ww = 0; ww < 8; ww++) Mg = fmaxf(Mg, pm[ww * 2]);
        float Sg = 0.f;
        float scl[8];
#pragma unroll
        for (int ww = 0; ww < 8; ww++) {
            scl[ww] = __expf(pm[ww * 2] - Mg);
            Sg += pm[ww * 2 + 1] * scl[ww];
        }
        float inv = 1.f / Sg;
        for (int h = tid; h < HH; h += 256) {
            float a = 0.f;
#pragma unroll
            for (int ww = 0; ww < 8; ww++) a += pp[ww * 512 + h] * scl[ww];
            g_ctxc[(size_t)(mhB * 8 + (h >> 6)) * 8192 +
                   (size_t)(((h & 63) >> 3) * 128 + rowB) * 8 + (h & 7)] =
                __float2half(a * inv);
        }
    }
    __syncthreads();
}

__global__ void __launch_bounds__(256, 1) dec_persistent(
    const float* __restrict__ Wdi, const float* __restrict__ Wdh,
    const float* __restrict__ bdi, const float* __restrict__ bdh,
    const float* __restrict__ Wfc, const float* __restrict__ bfc,
    float* __restrict__ out) {
    extern __shared__ __align__(16) char smc[];
    __half* Wsm = (__half*)smc;
    float* pa  = (float*)(smc + DOF_PA);
    float* pms = (float*)(smc + DOF_PMS);
    float* bqd = (float*)(smc + DOF_BQ);
    float* wd0 = (float*)(smc + DOF_WD0);
    uint32_t smb = smem_u32(smc);

    int bx = blockIdx.x, tid = threadIdx.x;
    int lane = tid & 31, wid = tid >> 5;
    int wm = wid >> 1, wn = wid & 1;
    int i4 = lane >> 3, r8 = lane & 7;
    int er = lane >> 2, ec = lane & 3;
    int mh = bx & 1;
    int nb8 = (bx >> 1) * 8;

    for (int idx = tid; idx < 32 * 256; idx += 256) {
        int cc = idx >> 8, k4 = (idx & 255) * 4;
        int gate = (cc & 1) | (((cc >> 3) & 1) << 1);
        int n = nb8 + ((cc >> 4) & 1) * 4 + ((cc >> 1) & 3);
        int row = gate * HH + n;
        float w4[4];
        if (k4 < HH) {
            const float* sp = Wdi + (size_t)row * (HH + 1) + 1 + k4;
            w4[0] = sp[0]; w4[1] = sp[1]; w4[2] = sp[2]; w4[3] = sp[3];
        } else {
            float4 wv = *(const float4*)(Wdh + (size_t)row * HH + (k4 - HH));
            w4[0] = wv.x; w4[1] = wv.y; w4[2] = wv.z; w4[3] = wv.w;
        }
        __half* d = Wsm + (size_t)cc * 1032 + k4;
        d[0] = __float2half(w4[0]); d[1] = __float2half(w4[1]);
        d[2] = __float2half(w4[2]); d[3] = __float2half(w4[3]);
    }
    if (tid < 32) {
        int nl = tid >> 2, g = tid & 3;
        int row = g * HH + nb8 + nl;
        bqd[nl * 4 + g] = bdi[row] + bdh[row];
        wd0[nl * 4 + g] = Wdi[(size_t)row * (HH + 1)];
    }
    if (tid == 0) {
#pragma unroll
        for (int p = 0; p < 4; p++) mbar_init(smb + DOF_MBAR + p * 8, 1);
    }
    __syncthreads();

    uint32_t albase = ((uint32_t)((i4 >> 1) & 1)) * 2048 +
                      (uint32_t)(wm * 32 + (i4 & 1) * 8 + r8) * 16;
    int bcol = wn * 16 + ((i4 >> 1) & 1) * 8 + r8;
    int bkh = (i4 & 1) * 8;

    float cst[4];
#pragma unroll
    for (int mi = 0; mi < 2; mi++)
#pragma unroll
        for (int rh = 0; rh < 2; rh++) {
            int b = mh * 128 + wm * 32 + mi * 16 + rh * 8 + er;
            cst[mi * 2 + rh] = g_c1f[(size_t)b * HH + nb8 + wn * 4 + ec];
        }

    unsigned cF[4] = {0, 0, 0, 0};
    unsigned round = 0;
    for (int ds = 0; ds <= PL; ds++) {
        const __half* p0 = g_ctxc + (size_t)mh * 8 * 8192;
        const __half* p1 = g_h1[ds & 1] + (size_t)mh * 8 * 8192;
        // prefetch h1-half (chunks 8..11) so they land during attention
        if (ds < PL && tid == 0) {
#pragma unroll
            for (int p = 0; p < 4; p++)
                issue_bulk(smb + DOF_AB + p * 16384, p1 + (size_t)p * 8192, 16384,
                           smb + DOF_MBAR + p * 8);
        }
        attn_two(ds, bx, ds < PL, Wfc, bfc, out, pa, pms);
        if (ds == PL) break;

        float acc[2][2][4];
#pragma unroll
        for (int a = 0; a < 2; a++)
#pragma unroll
            for (int b = 0; b < 2; b++)
#pragma unroll
                for (int qd = 0; qd < 4; qd++) acc[a][b][qd] = 0.f;

        // Wdh * h1 half (gemm chunks 8..15) — before the ctx barrier
        dec_half(p1, 8, smb, acc, cF, albase, bcol, bkh, tid);
        gridbar(&g_bar_dec, round, NBD);   // ctx ready, buffers free

        if (tid == 0) {
#pragma unroll
            for (int p = 0; p < 4; p++)
                issue_bulk(smb + DOF_AB + p * 16384, p0 + (size_t)p * 8192, 16384,
                           smb + DOF_MBAR + p * 8);
        }
        dec_half(p0, 0, smb, acc, cF, albase, bcol, bkh, tid);

        {
            int nl = wn * 4 + ec;
            int n = nb8 + nl;
            int kc = n >> 6;
            int seg = (n & 63) >> 3;
            __half* hb = g_h1[(ds + 1) & 1];
#pragma unroll
            for (int mi = 0; mi < 2; mi++)
#pragma unroll
                for (int rh = 0; rh < 2; rh++) {
                    int row = wm * 32 + mi * 16 + rh * 8 + er;
                    int b = mh * 128 + row;
                    float y = g_yprev[b];
                    const float* bp = bqd + nl * 4;
                    const float* wp = wd0 + nl * 4;
                    float g0 = acc[mi][0][rh * 2]     + bp[0] + wp[0] * y;
                    float g1 = acc[mi][0][rh * 2 + 1] + bp[1] + wp[1] * y;
                    float g2 = acc[mi][1][rh * 2]     + bp[2] + wp[2] * y;
                    float g3 = acc[mi][1][rh * 2 + 1] + bp[3] + wp[3] * y;
                    float ig = sigf(g0), fg = sigf(g1);
                    float gg = tanhf(g2), og = sigf(g3);
                    float cv = fg * cst[mi * 2 + rh] + ig * gg;
                    cst[mi * 2 + rh] = cv;
                    hb[(size_t)(mh * 8 + kc) * 8192 + (size_t)(seg * 128 + row) * 8 +
                       (n & 7)] = __float2half(og * tanhf(cv));
                }
        }
        gridbar(&g_bar_dec, round, NBD);
    }
}

extern "C" void kernel_launch(void* const* d_in, const int* in_sizes, int n_in,
                              void* d_out, int out_size) {
    const float* x    = (const float*)d_in[0];
    const float* Wih0 = (const float*)d_in[1];
    const float* Whh0 = (const float*)d_in[2];
    const float* bi0  = (const float*)d_in[3];
    const float* bh0  = (const float*)d_in[4];
    const float* Wih1 = (const float*)d_in[5];
    const float* Whh1 = (const float*)d_in[6];
    const float* bi1  = (const float*)d_in[7];
    const float* bh1  = (const float*)d_in[8];
    const float* Wdi  = (const float*)d_in[9];
    const float* Wdh  = (const float*)d_in[10];
    const float* bdi  = (const float*)d_in[11];
    const float* bdh  = (const float*)d_in[12];
    const float* Wfc  = (const float*)d_in[13];
    const float* bfc  = (const float*)d_in[14];
    float* out = (float*)d_out;

    cudaFuncSetAttribute(enc_persistent, cudaFuncAttributeMaxDynamicSharedMemorySize, ENC_SMEM);
    cudaFuncSetAttribute(dec_persistent, cudaFuncAttributeMaxDynamicSharedMemorySize, DEC_SMEM);

    prep_kernel<<<(BB * HH + 255) / 256, 256>>>();
    xp_kernel<<<dim3(LL, 128), 256>>>(x, Wih0, bi0, bh0);
    enc_persistent<<<NBE, 256, ENC_SMEM>>>(Whh0, Wih1, Whh1, bi1, bh1);
    dec_persistent<<<NBD, 256, DEC_SMEM>>>(Wdi, Wdh, bdi, bdh, Wfc, bfc, out);
}

// round 12
// speedup vs baseline: 1.6906x; 1.0439x over previous
#include <cuda_runtime.h>
#include <cuda_fp16.h>
#include <stdint.h>

#define BB 256
#define LL 336
#define NIN 8
#define HH 512
#define PL 96
#define NBE 128
#define NBD 128

// chunked h layout: [mh*8+kc] chunks of 8192 halves; within chunk:
// elem(row,klocal) at ((klocal>>3)*128 + row)*8 + (klocal&7)
__device__ __align__(128) __half g_h0[2][BB*HH];
__device__ __align__(128) __half g_h1[2][BB*HH];
__device__ __align__(128) __half g_ctxc[BB*HH];
__device__ float  g_c1f[BB*HH];
__device__ float  g_yprev[BB];
__device__ __align__(128) __half g_enc[(size_t)LL*BB*HH];     // [l][b][n]
__device__ __align__(128) __half g_xp[(size_t)LL*BB*2048];    // [s][cta128][row128][nl8][4]
__device__ unsigned g_bar_enc2[2], g_bar_dec2[2];

__device__ __forceinline__ float sigf(float x) { return 1.f / (1.f + __expf(-x)); }

__device__ __forceinline__ void gridbar(unsigned* bar, unsigned& round, unsigned nblk) {
    round++;
    __syncthreads();
    __threadfence();
    if (threadIdx.x == 0) {
        unsigned target = round * nblk;
        atomicAdd(bar, 1u);
        while (*(volatile unsigned*)bar < target) { }
        __threadfence();
    }
    __syncthreads();
}

__device__ __forceinline__ uint32_t smem_u32(const void* p) {
    uint32_t a;
    asm("{ .reg .u64 t; cvta.to.shared.u64 t, %1; cvt.u32.u64 %0, t; }" : "=r"(a) : "l"(p));
    return a;
}
__device__ __forceinline__ void mma16(float c[4], const uint32_t a[4], const uint32_t b[2]) {
    asm volatile(
        "mma.sync.aligned.m16n8k16.row.col.f32.f16.f16.f32 "
        "{%0,%1,%2,%3},{%4,%5,%6,%7},{%8,%9},{%0,%1,%2,%3};"
        : "+f"(c[0]), "+f"(c[1]), "+f"(c[2]), "+f"(c[3])
        : "r"(a[0]), "r"(a[1]), "r"(a[2]), "r"(a[3]), "r"(b[0]), "r"(b[1]));
}
#define LDSM4(r0, r1, r2, r3, addr) \
    asm volatile("ldmatrix.sync.aligned.m8n8.x4.shared.b16 {%0,%1,%2,%3},[%4];" \
                 : "=r"(r0), "=r"(r1), "=r"(r2), "=r"(r3) : "r"(addr))

__device__ __forceinline__ void mbar_init(uint32_t mbar, uint32_t cnt) {
    asm volatile("mbarrier.init.shared.b64 [%0], %1;" :: "r"(mbar), "r"(cnt) : "memory");
}
__device__ __forceinline__ void mbar_wait(uint32_t mbar, uint32_t parity) {
    uint32_t done = 0;
    while (!done) {
        asm volatile(
            "{\n\t.reg .pred p;\n\t"
            "mbarrier.try_wait.parity.acquire.cta.shared::cta.b64 p, [%1], %2, 0x989680;\n\t"
            "selp.b32 %0, 1, 0, p;\n\t}"
            : "=r"(done) : "r"(mbar), "r"(parity) : "memory");
    }
}
__device__ __forceinline__ void issue_bulk(uint32_t dst, const void* src, uint32_t bytes,
                                           uint32_t mbar) {
    asm volatile("mbarrier.arrive.expect_tx.shared.b64 _, [%0], %1;"
                 :: "r"(mbar), "r"(bytes) : "memory");
    asm volatile(
        "cp.async.bulk.shared::cluster.global.mbarrier::complete_tx::bytes [%0], [%1], %2, [%3];"
        :: "r"(dst), "l"(src), "r"(bytes), "r"(mbar) : "memory");
}

// ---------------- prep + xp ----------------
__global__ void prep_kernel() {
    int i = blockIdx.x * blockDim.x + threadIdx.x;
    if (i < BB * HH) {
        g_h0[0][i] = __float2half(0.f);
        g_h1[0][i] = __float2half(0.f);
    }
    if (i == 0) {
        g_bar_enc2[0] = 0u; g_bar_enc2[1] = 0u;
        g_bar_dec2[0] = 0u; g_bar_dec2[1] = 0u;
    }
}

__global__ void xp_kernel(const float* __restrict__ x, const float* __restrict__ Wih0,
                          const float* __restrict__ bi0, const float* __restrict__ bh0) {
    int s = blockIdx.x, c = blockIdx.y, tid = threadIdx.x;
    int mh = c & 1, nb = c >> 1;
    __shared__ float xs[128 * 8];
    __shared__ float Wq[8 * 4 * 8];
    __shared__ float bq[32];
    for (int idx = tid; idx < 1024; idx += 256) {
        int bl = idx >> 3, k = idx & 7;
        xs[idx] = x[((size_t)(mh * 128 + bl) * LL + s) * NIN + k];
    }
    if (tid < 256) {
        int nl = tid >> 5, g = (tid >> 3) & 3, k = tid & 7;
        Wq[tid] = Wih0[(g * HH + nb * 8 + nl) * NIN + k];
    }
    if (tid < 32) {
        int nl = tid >> 2, g = tid & 3;
        bq[tid] = bi0[g * HH + nb * 8 + nl] + bh0[g * HH + nb * 8 + nl];
    }
    __syncthreads();
    int row = tid & 127, part = tid >> 7;
    const float* xr = xs + row * 8;
    __half q16[16];
#pragma unroll
    for (int u = 0; u < 4; u++) {
        int nl = part * 4 + u;
#pragma unroll
        for (int g = 0; g < 4; g++) {
            const float* wr = Wq + (nl * 4 + g) * 8;
            float a = bq[nl * 4 + g];
#pragma unroll
            for (int k = 0; k < 8; k++) a += wr[k] * xr[k];
            q16[u * 4 + g] = __float2half(a);
        }
    }
    __half* dst = g_xp + ((size_t)s * 128 + c) * 4096 + row * 32 + part * 16;
    *(uint4*)(dst)     = *(uint4*)(q16);
    *(uint4*)(dst + 8) = *(uint4*)(q16 + 8);
}

// ---------------- ENCODER: unified 128 CTAs, 4-buffer ring, sync recycling ----------------
#define OF_WL1  33280
#define OF_AB   99328
#define OF_XP   164864
#define OF_HT0  173056
#define OF_HT1  175104
#define OF_B1   177152
#define OF_MBAR 177280
#define ENC_SMEM 177408

__global__ void __launch_bounds__(256, 1) enc_persistent(
    const float* __restrict__ Whh0, const float* __restrict__ Wih1,
    const float* __restrict__ Whh1,
    const float* __restrict__ bi1, const float* __restrict__ bh1) {
    extern __shared__ __align__(16) char smc[];
    __half* WL0 = (__half*)smc;
    __half* WL1 = (__half*)(smc + OF_WL1);
    __half* ht0 = (__half*)(smc + OF_HT0);
    __half* ht1 = (__half*)(smc + OF_HT1);
    float*  bq1 = (float*)(smc + OF_B1);
    uint32_t smb = smem_u32(smc);

    int bx = blockIdx.x, tid = threadIdx.x;
    int lane = tid & 31, wid = tid >> 5;
    int wm = wid >> 1, wn = wid & 1;
    int i4 = lane >> 3, r8 = lane & 7;
    int er = lane >> 2, ec = lane & 3;
    int mh = bx & 1, nb = bx >> 1;

    // ---- weights to smem (32 cols, gate-permuted) ----
    for (int idx = tid; idx < 32 * 128; idx += 256) {
        int cc = idx >> 7, k4 = (idx & 127) * 4;
        int gate = (cc & 1) | (((cc >> 3) & 1) << 1);
        int n = nb * 8 + ((cc >> 4) & 1) * 4 + ((cc >> 1) & 3);
        float4 w = *(const float4*)(Whh0 + (size_t)(gate * HH + n) * HH + k4);
        __half* d = WL0 + (size_t)cc * 520 + k4;
        d[0] = __float2half(w.x); d[1] = __float2half(w.y);
        d[2] = __float2half(w.z); d[3] = __float2half(w.w);
    }
    for (int idx = tid; idx < 32 * 256; idx += 256) {
        int cc = idx >> 8, k4 = (idx & 255) * 4;
        int gate = (cc & 1) | (((cc >> 3) & 1) << 1);
        int n = nb * 8 + ((cc >> 4) & 1) * 4 + ((cc >> 1) & 3);
        int row = gate * HH + n;
        const float* srcW = (k4 < HH) ? Wih1 + (size_t)row * HH + k4
                                      : Whh1 + (size_t)row * HH + (k4 - HH);
        float4 w = *(const float4*)srcW;
        __half* d = WL1 + (size_t)cc * 1032 + k4;
        d[0] = __float2half(w.x); d[1] = __float2half(w.y);
        d[2] = __float2half(w.z); d[3] = __float2half(w.w);
    }
    if (tid < 32) {
        int nl = tid >> 2, g = tid & 3;
        int n = nb * 8 + nl;
        bq1[tid] = bi1[g * HH + n] + bh1[g * HH + n];
    }
    if (tid == 0) {
#pragma unroll
        for (int p = 0; p < 4; p++) mbar_init(smb + OF_MBAR + p * 8, 1);
        mbar_init(smb + OF_MBAR + 32, 1);   // xp
    }
    __syncthreads();

    uint32_t albase = ((uint32_t)((i4 >> 1) & 1)) * 2048 +
                      (uint32_t)(wm * 32 + (i4 & 1) * 8 + r8) * 16;
    int bcol = wn * 16 + ((i4 >> 1) & 1) * 8 + r8;
    int bkh = (i4 & 1) * 8;
    uint32_t bo0 = smb + (uint32_t)(bcol * 520 + bkh) * 2;
    uint32_t bo1 = smb + OF_WL1 + (uint32_t)(bcol * 1032 + bkh) * 2;

    float cst0[4], cst1[4];
#pragma unroll
    for (int i = 0; i < 4; i++) { cst0[i] = 0.f; cst1[i] = 0.f; }

    unsigned cF[4] = {0, 0, 0, 0}, cXP = 0;
    unsigned round = 0;
    for (int s = 0; s <= LL; s++) {
        bool doL0 = (s < LL), doL1 = (s >= 1);
        int nch = doL1 ? 16 : 8;
        const __half* p0 = g_h0[s & 1] + (size_t)mh * 8 * 8192;
        const __half* p1 = g_h1[(s + 1) & 1] + (size_t)mh * 8 * 8192;

        if (tid == 0) {
            if (doL0)
                issue_bulk(smb + OF_XP, g_xp + ((size_t)s * 128 + bx) * 4096, 8192,
                           smb + OF_MBAR + 32);
#pragma unroll
            for (int p = 0; p < 4; p++)
                issue_bulk(smb + OF_AB + p * 16384, p0 + (size_t)p * 8192, 16384,
                           smb + OF_MBAR + p * 8);
        }

        float aL0[2][2][4], aL1[2][2][4];
#pragma unroll
        for (int a = 0; a < 2; a++)
#pragma unroll
            for (int b = 0; b < 2; b++)
#pragma unroll
                for (int q = 0; q < 4; q++) { aL0[a][b][q] = 0.f; aL1[a][b][q] = 0.f; }

        for (int kc = 0; kc < nch; kc++) {
            int p = kc & 3;
            mbar_wait(smb + OF_MBAR + p * 8, cF[p] & 1);
            cF[p]++;
            bool dL0 = doL0 && kc < 8;
            uint32_t ab = smb + OF_AB + p * 16384;
            uint32_t kb = (uint32_t)(kc * 128);
#pragma unroll
            for (int j = 0; j < 4; j++) {
                uint32_t a[2][4];
                LDSM4(a[0][0], a[0][1], a[0][2], a[0][3], ab + albase + j * 4096);
                LDSM4(a[1][0], a[1][1], a[1][2], a[1][3], ab + albase + j * 4096 + 256);
                if (dL0) {
                    uint32_t b[4];
                    LDSM4(b[0], b[1], b[2], b[3], bo0 + kb + j * 32);
                    mma16(aL0[0][0], a[0], b);     mma16(aL0[0][1], a[0], b + 2);
                    mma16(aL0[1][0], a[1], b);     mma16(aL0[1][1], a[1], b + 2);
                }
                if (doL1) {
                    uint32_t b[4];
                    LDSM4(b[0], b[1], b[2], b[3], bo1 + kb + j * 32);
                    mma16(aL1[0][0], a[0], b);     mma16(aL1[0][1], a[0], b + 2);
                    mma16(aL1[1][0], a[1], b);     mma16(aL1[1][1], a[1], b + 2);
                }
            }
            __syncthreads();   // all warps done reading buffer p
            if (tid == 0 && kc + 4 < nch) {
                int nk = kc + 4;
                const __half* sp = (nk < 8) ? p0 + (size_t)nk * 8192
                                            : p1 + (size_t)(nk - 8) * 8192;
                issue_bulk(ab, sp, 16384, smb + OF_MBAR + p * 8);
            }
        }

        // ---- fused cells ----
        int nl = wn * 4 + ec;
        if (doL0) {
            mbar_wait(smb + OF_MBAR + 32, cXP & 1);
            cXP++;
            const __half* xpb = (const __half*)(smc + OF_XP);
#pragma unroll
            for (int mi = 0; mi < 2; mi++)
#pragma unroll
                for (int rh = 0; rh < 2; rh++) {
                    int row = wm * 32 + mi * 16 + rh * 8 + er;
                    uint2 xu = *(const uint2*)(xpb + row * 32 + nl * 4);
                    const __half* xh = (const __half*)&xu;
                    float g0 = aL0[mi][0][rh * 2]     + __half2float(xh[0]);
                    float g1 = aL0[mi][0][rh * 2 + 1] + __half2float(xh[1]);
                    float g2 = aL0[mi][1][rh * 2]     + __half2float(xh[2]);
                    float g3 = aL0[mi][1][rh * 2 + 1] + __half2float(xh[3]);
                    float ig = sigf(g0), fg = sigf(g1);
                    float gg = tanhf(g2), og = sigf(g3);
                    int ix = mi * 2 + rh;
                    float cv = fg * cst0[ix] + ig * gg;
                    cst0[ix] = cv;
                    ht0[row * 8 + nl] = __float2half(og * tanhf(cv));
                }
        }
        if (doL1) {
            const float* bp = bq1 + nl * 4;
#pragma unroll
            for (int mi = 0; mi < 2; mi++)
#pragma unroll
                for (int rh = 0; rh < 2; rh++) {
                    int row = wm * 32 + mi * 16 + rh * 8 + er;
                    float g0 = aL1[mi][0][rh * 2]     + bp[0];
                    float g1 = aL1[mi][0][rh * 2 + 1] + bp[1];
                    float g2 = aL1[mi][1][rh * 2]     + bp[2];
                    float g3 = aL1[mi][1][rh * 2 + 1] + bp[3];
                    float ig = sigf(g0), fg = sigf(g1);
                    float gg = tanhf(g2), og = sigf(g3);
                    int ix = mi * 2 + rh;
                    float cv = fg * cst1[ix] + ig * gg;
                    cst1[ix] = cv;
                    ht1[row * 8 + nl] = __float2half(og * tanhf(cv));
                    if (s == LL)
                        g_c1f[(size_t)(mh * 128 + row) * HH + nb * 8 + nl] = cv;
                }
        }
        __syncthreads();
        if (doL0 && tid < 128) {
            uint4 v = *(uint4*)(ht0 + tid * 8);
            *(uint4*)(g_h0[(s + 1) & 1] + (size_t)(mh * 8 + (nb >> 3)) * 8192 +
                      (size_t)((nb & 7) * 128 + tid) * 8) = v;
        }
        if (doL1 && tid >= 128) {
            int row = tid - 128;
            uint4 v = *(uint4*)(ht1 + row * 8);
            *(uint4*)(g_h1[s & 1] + (size_t)(mh * 8 + (nb >> 3)) * 8192 +
                      (size_t)((nb & 7) * 128 + row) * 8) = v;
            *(uint4*)(g_enc + (size_t)(s - 1) * BB * HH +
                      (size_t)(mh * 128 + row) * HH + nb * 8) = v;
        }
        gridbar(&g_bar_enc2[mh], round, 64);
    }
}

// ---------------- DECODER ----------------
#define DOF_AB   66048
#define DOF_PA   131584
#define DOF_PMS  164352
#define DOF_BQ   164480
#define DOF_WD0  164608
#define DOF_MBAR 164736
#define DEC_SMEM 164864

template<int NQ, int KPAD>
__device__ __forceinline__ void mma_chunk(uint32_t abuf, uint32_t wsm, int kglob,
                                          float (&acc)[2][NQ*2][4],
                                          uint32_t albase, int bcol, int bkh) {
#pragma unroll
    for (int j = 0; j < 4; j++) {
        uint32_t a[2][4];
#pragma unroll
        for (int mi = 0; mi < 2; mi++)
            LDSM4(a[mi][0], a[mi][1], a[mi][2], a[mi][3],
                  abuf + albase + j * 4096 + mi * 256);
#pragma unroll
        for (int q = 0; q < NQ; q++) {
            uint32_t b[4];
            LDSM4(b[0], b[1], b[2], b[3],
                  wsm + (uint32_t)((bcol + q * 32) * KPAD + kglob + j * 16 + bkh) * 2);
#pragma unroll
            for (int mi = 0; mi < 2; mi++) {
                mma16(acc[mi][q * 2 + 0], a[mi], b);
                mma16(acc[mi][q * 2 + 1], a[mi], b + 2);
            }
        }
    }
}

// one 8-chunk half; buffers recycled via __syncthreads
__device__ __forceinline__ void dec_half(const __half* base, int kc0, uint32_t smb,
                                         float (&acc)[2][2][4], unsigned (&cF)[4],
                                         uint32_t albase, int bcol, int bkh, int tid) {
    for (int i = 0; i < 8; i++) {
        int p = i & 3;
        mbar_wait(smb + DOF_MBAR + p * 8, cF[p] & 1);
        cF[p]++;
        mma_chunk<1, 1032>(smb + DOF_AB + p * 16384, smb, (kc0 + i) * 64, acc,
                           albase, bcol, bkh);
        __syncthreads();
        if (tid == 0 && i + 4 < 8)
            issue_bulk(smb + DOF_AB + p * 16384, base + (size_t)(i + 4) * 8192, 16384,
                       smb + DOF_MBAR + p * 8);
    }
}

__device__ __forceinline__ float dot8r(uint4 v, const float* s) {
    const __half2* h2 = (const __half2*)&v;
    float r = 0.f;
#pragma unroll
    for (int i = 0; i < 4; i++) {
        float2 f = __half22float2(h2[i]);
        r += f.x * s[2 * i] + f.y * s[2 * i + 1];
    }
    return r;
}
// lazy-rescale online softmax update: branch is warp-uniform (s1 uniform post-reduce)
__device__ __forceinline__ void online_upd(float& M, float& S, float* C,
                                           float s1, uint4 v0, uint4 v1) {
    float e;
    if (s1 > M) {
        float r = __expf(M - s1);
        S *= r;
#pragma unroll
        for (int i = 0; i < 16; i++) C[i] *= r;
        M = s1;
        e = 1.f;
    } else {
        e = __expf(s1 - M);
    }
    S += e;
    const __half2* ha = (const __half2*)&v0;
    const __half2* hb = (const __half2*)&v1;
#pragma unroll
    for (int i = 0; i < 4; i++) {
        float2 f = __half22float2(ha[i]);
        C[2 * i]     += e * f.x;
        C[2 * i + 1] += e * f.y;
        float2 f2 = __half22float2(hb[i]);
        C[8 + 2 * i]     += e * f2.x;
        C[8 + 2 * i + 1] += e * f2.y;
    }
}

// both batches (b0, b0+64, same mh half) in one interleaved pass
__device__ void attn_two(int ds, int b0, int b1, bool full, const float* __restrict__ Wfc,
                         const float* __restrict__ bfc, float* __restrict__ out,
                         float* pa, float* pms) {
    int tid = threadIdx.x, lane = tid & 31, w = tid >> 5;
    const __half* h1b = g_h1[ds & 1];
    float hr0[16], hr1[16];
    {
        int mhB = b0 >> 7, rowB = b0 & 127;
        uint4 v0 = *(const uint4*)(h1b + (size_t)(mhB * 8 + (lane >> 3)) * 8192 +
                                   (size_t)((lane & 7) * 128 + rowB) * 8);
        uint4 v1 = *(const uint4*)(h1b + (size_t)(mhB * 8 + 4 + (lane >> 3)) * 8192 +
                                   (size_t)((lane & 7) * 128 + rowB) * 8);
        const __half* ha = (const __half*)&v0;
        const __half* hb = (const __half*)&v1;
#pragma unroll
        for (int i = 0; i < 8; i++) {
            hr0[i] = __half2float(ha[i]);
            hr0[8 + i] = __half2float(hb[i]);
        }
    }
    {
        int mhB = b1 >> 7, rowB = b1 & 127;
        uint4 v0 = *(const uint4*)(h1b + (size_t)(mhB * 8 + (lane >> 3)) * 8192 +
                                   (size_t)((lane & 7) * 128 + rowB) * 8);
        uint4 v1 = *(const uint4*)(h1b + (size_t)(mhB * 8 + 4 + (lane >> 3)) * 8192 +
                                   (size_t)((lane & 7) * 128 + rowB) * 8);
        const __half* ha = (const __half*)&v0;
        const __half* hb = (const __half*)&v1;
#pragma unroll
        for (int i = 0; i < 8; i++) {
            hr1[i] = __half2float(ha[i]);
            hr1[8 + i] = __half2float(hb[i]);
        }
    }
    if (w == 0) {
        float yv = 0.f;
#pragma unroll
        for (int i = 0; i < 8; i++)
            yv += hr0[i] * Wfc[lane * 8 + i] + hr0[8 + i] * Wfc[256 + lane * 8 + i];
#pragma unroll
        for (int off = 16; off; off >>= 1) yv += __shfl_xor_sync(0xffffffffu, yv, off);
        if (lane == 0) {
            float y = yv + bfc[0];
            if (ds > 0) out[b0 * PL + ds - 1] = y;
            g_yprev[b0] = (ds == 0) ? 0.f : y;
        }
    } else if (w == 1) {
        float yv = 0.f;
#pragma unroll
        for (int i = 0; i < 8; i++)
            yv += hr1[i] * Wfc[lane * 8 + i] + hr1[8 + i] * Wfc[256 + lane * 8 + i];
#pragma unroll
        for (int off = 16; off; off >>= 1) yv += __shfl_xor_sync(0xffffffffu, yv, off);
        if (lane == 0) {
            float y = yv + bfc[0];
            if (ds > 0) out[b1 * PL + ds - 1] = y;
            g_yprev[b1] = (ds == 0) ? 0.f : y;
        }
    }
    if (!full) return;

    float M0 = -1e30f, S0 = 0.f, C0[16];
    float M1 = -1e30f, S1 = 0.f, C1[16];
#pragma unroll
    for (int i = 0; i < 16; i++) { C0[i] = 0.f; C1[i] = 0.f; }
#pragma unroll 2
    for (int l = w; l < LL; l += 8) {
        const uint4* e0 = (const uint4*)(g_enc + ((size_t)l * BB + b0) * HH);
        const uint4* e1 = (const uint4*)(g_enc + ((size_t)l * BB + b1) * HH);
        uint4 v00 = e0[lane], v01 = e0[lane + 32];
        uint4 v10 = e1[lane], v11 = e1[lane + 32];
        float s0 = dot8r(v00, hr0) + dot8r(v01, hr0 + 8);
        float s1 = dot8r(v10, hr1) + dot8r(v11, hr1 + 8);
#pragma unroll
        for (int off = 16; off; off >>= 1) {
            s0 += __shfl_xor_sync(0xffffffffu, s0, off);
            s1 += __shfl_xor_sync(0xffffffffu, s1, off);
        }
        online_upd(M0, S0, C0, s0, v00, v01);
        online_upd(M1, S1, C1, s1, v10, v11);
    }
    if (lane == 0) {
        pms[w * 2] = M0;      pms[w * 2 + 1] = S0;
        pms[16 + w * 2] = M1; pms[16 + w * 2 + 1] = S1;
    }
#pragma unroll
    for (int i = 0; i < 8; i++) {
        pa[w * 512 + lane * 8 + i]       = C0[i];
        pa[w * 512 + 256 + lane * 8 + i] = C0[8 + i];
        pa[4096 + w * 512 + lane * 8 + i]       = C1[i];
        pa[4096 + w * 512 + 256 + lane * 8 + i] = C1[8 + i];
    }
    __syncthreads();
#pragma unroll
    for (int bb = 0; bb < 2; bb++) {
        int b = bb ? b1 : b0;
        int mhB = b >> 7, rowB = b & 127;
        const float* pm = pms + bb * 16;
        const float* pp = pa + bb * 4096;
        float Mg = -1e30f;
#pragma unroll
        for (int ww = 0; ww < 8; ww++) Mg = fmaxf(Mg, pm[ww * 2]);
        float Sg = 0.f;
        float scl[8];
#pragma unroll
        for (int ww = 0; ww < 8; ww++) {
            scl[ww] = __expf(pm[ww * 2] - Mg);
            Sg += pm[ww * 2 + 1] * scl[ww];
        }
        float inv = 1.f / Sg;
        for (int h = tid; h < HH; h += 256) {
            float a = 0.f;
#pragma unroll
            for (int ww = 0; ww < 8; ww++) a += pp[ww * 512 + h] * scl[ww];
            g_ctxc[(size_t)(mhB * 8 + (h >> 6)) * 8192 +
                   (size_t)(((h & 63) >> 3) * 128 + rowB) * 8 + (h & 7)] =
                __float2half(a * inv);
        }
    }
    __syncthreads();
}

__global__ void __launch_bounds__(256, 1) dec_persistent(
    const float* __restrict__ Wdi, const float* __restrict__ Wdh,
    const float* __restrict__ bdi, const float* __restrict__ bdh,
    const float* __restrict__ Wfc, const float* __restrict__ bfc,
    float* __restrict__ out) {
    extern __shared__ __align__(16) char smc[];
    __half* Wsm = (__half*)smc;
    float* pa  = (float*)(smc + DOF_PA);
    float* pms = (float*)(smc + DOF_PMS);
    float* bqd = (float*)(smc + DOF_BQ);
    float* wd0 = (float*)(smc + DOF_WD0);
    uint32_t smb = smem_u32(smc);

    int bx = blockIdx.x, tid = threadIdx.x;
    int lane = tid & 31, wid = tid >> 5;
    int wm = wid >> 1, wn = wid & 1;
    int i4 = lane >> 3, r8 = lane & 7;
    int er = lane >> 2, ec = lane & 3;
    int mh = bx & 1;
    int nb8 = (bx >> 1) * 8;
    // attention batches within own mh half (fully decoupled halves)
    int ab0 = mh * 128 + (bx >> 1);
    int ab1 = ab0 + 64;

    for (int idx = tid; idx < 32 * 256; idx += 256) {
        int cc = idx >> 8, k4 = (idx & 255) * 4;
        int gate = (cc & 1) | (((cc >> 3) & 1) << 1);
        int n = nb8 + ((cc >> 4) & 1) * 4 + ((cc >> 1) & 3);
        int row = gate * HH + n;
        float w4[4];
        if (k4 < HH) {
            const float* sp = Wdi + (size_t)row * (HH + 1) + 1 + k4;
            w4[0] = sp[0]; w4[1] = sp[1]; w4[2] = sp[2]; w4[3] = sp[3];
        } else {
            float4 wv = *(const float4*)(Wdh + (size_t)row * HH + (k4 - HH));
            w4[0] = wv.x; w4[1] = wv.y; w4[2] = wv.z; w4[3] = wv.w;
        }
        __half* d = Wsm + (size_t)cc * 1032 + k4;
        d[0] = __float2half(w4[0]); d[1] = __float2half(w4[1]);
        d[2] = __float2half(w4[2]); d[3] = __float2half(w4[3]);
    }
    if (tid < 32) {
        int nl = tid >> 2, g = tid & 3;
        int row = g * HH + nb8 + nl;
        bqd[nl * 4 + g] = bdi[row] + bdh[row];
        wd0[nl * 4 + g] = Wdi[(size_t)row * (HH + 1)];
    }
    if (tid == 0) {
#pragma unroll
        for (int p = 0; p < 4; p++) mbar_init(smb + DOF_MBAR + p * 8, 1);
    }
    __syncthreads();

    uint32_t albase = ((uint32_t)((i4 >> 1) & 1)) * 2048 +
                      (uint32_t)(wm * 32 + (i4 & 1) * 8 + r8) * 16;
    int bcol = wn * 16 + ((i4 >> 1) & 1) * 8 + r8;
    int bkh = (i4 & 1) * 8;

    float cst[4];
#pragma unroll
    for (int mi = 0; mi < 2; mi++)
#pragma unroll
        for (int rh = 0; rh < 2; rh++) {
            int b = mh * 128 + wm * 32 + mi * 16 + rh * 8 + er;
            cst[mi * 2 + rh] = g_c1f[(size_t)b * HH + nb8 + wn * 4 + ec];
        }

    unsigned cF[4] = {0, 0, 0, 0};
    unsigned round = 0;
    for (int ds = 0; ds <= PL; ds++) {
        const __half* p0 = g_ctxc + (size_t)mh * 8 * 8192;
        const __half* p1 = g_h1[ds & 1] + (size_t)mh * 8 * 8192;
        // prefetch h1-half (chunks 8..11) so they land during attention
        if (ds < PL && tid == 0) {
#pragma unroll
            for (int p = 0; p < 4; p++)
                issue_bulk(smb + DOF_AB + p * 16384, p1 + (size_t)p * 8192, 16384,
                           smb + DOF_MBAR + p * 8);
        }
        attn_two(ds, ab0, ab1, ds < PL, Wfc, bfc, out, pa, pms);
        if (ds == PL) break;

        float acc[2][2][4];
#pragma unroll
        for (int a = 0; a < 2; a++)
#pragma unroll
            for (int b = 0; b < 2; b++)
#pragma unroll
                for (int qd = 0; qd < 4; qd++) acc[a][b][qd] = 0.f;

        // Wdh * h1 half (gemm chunks 8..15) — before the ctx barrier
        dec_half(p1, 8, smb, acc, cF, albase, bcol, bkh, tid);
        gridbar(&g_bar_dec2[mh], round, 64);   // ctx ready, buffers free

        if (tid == 0) {
#pragma unroll
            for (int p = 0; p < 4; p++)
                issue_bulk(smb + DOF_AB + p * 16384, p0 + (size_t)p * 8192, 16384,
                           smb + DOF_MBAR + p * 8);
        }
        dec_half(p0, 0, smb, acc, cF, albase, bcol, bkh, tid);

        {
            int nl = wn * 4 + ec;
            int n = nb8 + nl;
            int kc = n >> 6;
            int seg = (n & 63) >> 3;
            __half* hb = g_h1[(ds + 1) & 1];
#pragma unroll
            for (int mi = 0; mi < 2; mi++)
#pragma unroll
                for (int rh = 0; rh < 2; rh++) {
                    int row = wm * 32 + mi * 16 + rh * 8 + er;
                    int b = mh * 128 + row;
                    float y = g_yprev[b];
                    const float* bp = bqd + nl * 4;
                    const float* wp = wd0 + nl * 4;
                    float g0 = acc[mi][0][rh * 2]     + bp[0] + wp[0] * y;
                    float g1 = acc[mi][0][rh * 2 + 1] + bp[1] + wp[1] * y;
                    float g2 = acc[mi][1][rh * 2]     + bp[2] + wp[2] * y;
                    float g3 = acc[mi][1][rh * 2 + 1] + bp[3] + wp[3] * y;
                    float ig = sigf(g0), fg = sigf(g1);
                    float gg = tanhf(g2), og = sigf(g3);
                    float cv = fg * cst[mi * 2 + rh] + ig * gg;
                    cst[mi * 2 + rh] = cv;
                    hb[(size_t)(mh * 8 + kc) * 8192 + (size_t)(seg * 128 + row) * 8 +
                       (n & 7)] = __float2half(og * tanhf(cv));
                }
        }
        gridbar(&g_bar_dec2[mh], round, 64);
    }
}

extern "C" void kernel_launch(void* const* d_in, const int* in_sizes, int n_in,
                              void* d_out, int out_size) {
    const float* x    = (const float*)d_in[0];
    const float* Wih0 = (const float*)d_in[1];
    const float* Whh0 = (const float*)d_in[2];
    const float* bi0  = (const float*)d_in[3];
    const float* bh0  = (const float*)d_in[4];
    const float* Wih1 = (const float*)d_in[5];
    const float* Whh1 = (const float*)d_in[6];
    const float* bi1  = (const float*)d_in[7];
    const float* bh1  = (const float*)d_in[8];
    const float* Wdi  = (const float*)d_in[9];
    const float* Wdh  = (const float*)d_in[10];
    const float* bdi  = (const float*)d_in[11];
    const float* bdh  = (const float*)d_in[12];
    const float* Wfc  = (const float*)d_in[13];
    const float* bfc  = (const float*)d_in[14];
    float* out = (float*)d_out;

    cudaFuncSetAttribute(enc_persistent, cudaFuncAttributeMaxDynamicSharedMemorySize, ENC_SMEM);
    cudaFuncSetAttribute(dec_persistent, cudaFuncAttributeMaxDynamicSharedMemorySize, DEC_SMEM);

    prep_kernel<<<(BB * HH + 255) / 256, 256>>>();
    xp_kernel<<<dim3(LL, 128), 256>>>(x, Wih0, bi0, bh0);
    enc_persistent<<<NBE, 256, ENC_SMEM>>>(Whh0, Wih1, Whh1, bi1, bh1);
    dec_persistent<<<NBD, 256, DEC_SMEM>>>(Wdi, Wdh, bdi, bdh, Wfc, bfc, out);
}